// round 9
// baseline (speedup 1.0000x reference)
#include <cuda_runtime.h>
#include <cstdint>

#define B_ 4
#define L_ 4096
#define D_ 1024
#define H_ 16
#define W_ 64
#define HD_ 64
#define ML_ (B_*L_)      // 16384 rows
#define EPS_ 1e-5f

// Scratch (allocation-free rule: __device__ globals)
__device__ float g_qkv [(size_t)ML_ * 3 * D_];   // [B*L, 3*D] (tf32-rounded)
__device__ float g_attn[(size_t)ML_ * D_];       // [B*L, D]   (tf32-rounded)
__device__ float g_y   [(size_t)ML_ * D_];       // pre-LN residual sum
__device__ float g_xr  [(size_t)ML_ * D_];       // x rounded to tf32
__device__ float g_wq  [(size_t)3 * D_ * D_];    // Wqkv rounded
__device__ float g_wp  [(size_t)D_ * D_];        // Wproj rounded

// ---------------------------------------------------------------------------
__device__ __forceinline__ uint32_t f2tf32(float f) {
    uint32_t u;
    asm("cvt.rna.tf32.f32 %0, %1;" : "=r"(u) : "f"(f));
    return u;
}
__device__ __forceinline__ float rtf32(float f) {
    return __uint_as_float(f2tf32(f));
}
__device__ __forceinline__ uint32_t smem_u32(const void* p) {
    uint32_t a;
    asm("{ .reg .u64 t; cvta.to.shared.u64 t, %1; cvt.u32.u64 %0, t; }"
        : "=r"(a) : "l"(p));
    return a;
}
__device__ __forceinline__ void cp16(uint32_t dst, const void* src) {
    asm volatile("cp.async.cg.shared.global [%0], [%1], 16;"
                 :: "r"(dst), "l"(src) : "memory");
}
__device__ __forceinline__ void mma_16x8x8_tf32(float* c, const uint32_t* a,
                                                const uint32_t* b) {
    asm volatile(
        "mma.sync.aligned.m16n8k8.row.col.f32.tf32.tf32.f32 "
        "{%0,%1,%2,%3}, {%4,%5,%6,%7}, {%8,%9}, {%0,%1,%2,%3};"
        : "+f"(c[0]), "+f"(c[1]), "+f"(c[2]), "+f"(c[3])
        : "r"(a[0]), "r"(a[1]), "r"(a[2]), "r"(a[3]), "r"(b[0]), "r"(b[1]));
}
// ldmatrix x4 b16: viewed as b32, r_i[lane l] = tile_i[l>>2][l&3] where
// tile_i is addressed by lanes 8i..8i+7 (lane j -> row j of the 8x(16B) tile).
__device__ __forceinline__ void ldsm4(uint32_t* r, uint32_t addr) {
    asm volatile("ldmatrix.sync.aligned.m8n8.x4.shared.b16 {%0,%1,%2,%3}, [%4];"
                 : "=r"(r[0]), "=r"(r[1]), "=r"(r[2]), "=r"(r[3]) : "r"(addr));
}

// ---------------------------------------------------------------------------
// Elementwise tf32 rounding prepass
// ---------------------------------------------------------------------------
__global__ void round_tf32(const float* __restrict__ in, float* __restrict__ out,
                           int n4)
{
    int i = blockIdx.x * blockDim.x + threadIdx.x;
    if (i < n4) {
        float4 v = ((const float4*)in)[i];
        v.x = rtf32(v.x); v.y = rtf32(v.y); v.z = rtf32(v.z); v.w = rtf32(v.w);
        ((float4*)out)[i] = v;
    }
}

// ---------------------------------------------------------------------------
// Tensor-core GEMM via mma.sync + cp.async + ldmatrix.
// CTA 128x128, K-tile 32, 3-stage cp.async, 2 CTAs/SM.
// Full A+B fragment double-buffering: only the first fragment set after each
// barrier has exposed LDSM->MMA latency.
// ---------------------------------------------------------------------------
#define TS 36
#define BUFW (128*TS*2)          // words per stage (A then B)
#define GEMM_SMEM (3*BUFW*4)     // 110592 B

template<int RESID, int ROUND>
__global__ void __launch_bounds__(256, 2) gemm_mma(
    const float* __restrict__ A, const float* __restrict__ Bw,
    const float* __restrict__ bias, const float* __restrict__ R,
    float* __restrict__ C, int M, int N, int K)
{
    extern __shared__ float sm[];
    const uint32_t sbase = smem_u32(sm);
    const int tid  = threadIdx.x;
    const int wid  = tid >> 5, lane = tid & 31;
    const int g    = lane >> 2, tg = lane & 3;
    const int wm   = (wid >> 2) << 6;
    const int wn   = (wid & 3) << 5;
    const int bm   = blockIdx.y << 7, bn = blockIdx.x << 7;
    const int r0   = tid >> 3, c0 = (tid & 7) << 2;
    const int ntk  = K >> 5;

    // ldmatrix per-lane byte offsets (within a stage buffer)
    const int lrA = lane & 15;                  // row-within-16
    const int lcA = (lane >> 4) << 2;           // col 0 or 4 (words)
    uint32_t aoff[2];
#pragma unroll
    for (int mh = 0; mh < 2; mh++)
        aoff[mh] = (uint32_t)(((wm + (mh << 4) + lrA) * TS + lcA) << 2);
    const int lrB = ((lane >> 4) << 3) + (lane & 7);
    const int lcB = ((lane >> 3) & 1) << 2;
    uint32_t boff[2];
#pragma unroll
    for (int p = 0; p < 2; p++)
        boff[p] = (uint32_t)(((wn + (p << 4) + lrB) * TS + lcB) << 2);

    float acc[4][4][4];
#pragma unroll
    for (int mi = 0; mi < 4; mi++)
#pragma unroll
        for (int ni = 0; ni < 4; ni++)
#pragma unroll
            for (int i = 0; i < 4; i++) acc[mi][ni][i] = 0.f;

    auto cp_tile = [&](int kt, int buf) {
        const int kc = kt << 5;
        const uint32_t da = sbase + (uint32_t)((buf * BUFW + r0 * TS + c0) << 2);
        const uint32_t db = da + (uint32_t)((128 * TS) << 2);
#pragma unroll
        for (int i = 0; i < 4; i++) {
            cp16(da + (uint32_t)((i << 5) * TS << 2),
                 A  + (size_t)(bm + r0 + (i << 5)) * K + kc + c0);
            cp16(db + (uint32_t)((i << 5) * TS << 2),
                 Bw + (size_t)(bn + r0 + (i << 5)) * K + kc + c0);
        }
        asm volatile("cp.async.commit_group;" ::: "memory");
    };

    cp_tile(0, 0);
    if (ntk > 1) cp_tile(1, 1);

    int buf = 0;
    for (int kt = 0; kt < ntk; kt++) {
        if (kt < ntk - 1)
            asm volatile("cp.async.wait_group 1;" ::: "memory");
        else
            asm volatile("cp.async.wait_group 0;" ::: "memory");
        __syncthreads();

        const uint32_t Ab = sbase + (uint32_t)((buf * BUFW) << 2);
        const uint32_t Bb = Ab + (uint32_t)((128 * TS) << 2);

        // fragment pipeline: preload ks=0 A and B
        uint32_t afb[2][4][4], bfb[2][4][2];
#pragma unroll
        for (int mi = 0; mi < 4; mi++)
            ldsm4(afb[0][mi], Ab + aoff[mi & 1]
                          + (uint32_t)((mi >> 1) * ((TS << 5) << 2)));
#pragma unroll
        for (int p = 0; p < 2; p++) {
            uint32_t t4[4];
            ldsm4(t4, Bb + boff[p]);
            bfb[0][2*p][0]   = t4[0]; bfb[0][2*p][1]   = t4[1];
            bfb[0][2*p+1][0] = t4[2]; bfb[0][2*p+1][1] = t4[3];
        }

#pragma unroll
        for (int ks = 0; ks < 4; ks++) {
            const int cb = ks & 1, nb2 = cb ^ 1;
            if (ks < 3) {
                const uint32_t kb2 = (uint32_t)((ks + 1) << 5);
#pragma unroll
                for (int mi = 0; mi < 4; mi++)
                    ldsm4(afb[nb2][mi], Ab + aoff[mi & 1]
                                  + (uint32_t)((mi >> 1) * ((TS << 5) << 2)) + kb2);
#pragma unroll
                for (int p = 0; p < 2; p++) {
                    uint32_t t4[4];
                    ldsm4(t4, Bb + boff[p] + kb2);
                    bfb[nb2][2*p][0]   = t4[0]; bfb[nb2][2*p][1]   = t4[1];
                    bfb[nb2][2*p+1][0] = t4[2]; bfb[nb2][2*p+1][1] = t4[3];
                }
            }
#pragma unroll
            for (int ni = 0; ni < 4; ni++)
#pragma unroll
                for (int mi = 0; mi < 4; mi++)
                    mma_16x8x8_tf32(acc[mi][ni], afb[cb][mi], bfb[cb][ni]);

            // issue next-stage cp.async after first MMA batch (tensor pipe hot)
            if (ks == 0 && kt + 2 < ntk) {
                int nb = buf + 2; if (nb >= 3) nb -= 3;
                cp_tile(kt + 2, nb);
            }
        }
        if (++buf == 3) buf = 0;
    }

#pragma unroll
    for (int mi = 0; mi < 4; mi++) {
#pragma unroll
        for (int ni = 0; ni < 4; ni++) {
            const int row = bm + wm + (mi << 4) + g;
            const int col = bn + wn + (ni << 3) + (tg << 1);
            float2 bb = *(const float2*)(bias + col);
            float2 v0 = make_float2(acc[mi][ni][0] + bb.x, acc[mi][ni][1] + bb.y);
            float2 v1 = make_float2(acc[mi][ni][2] + bb.x, acc[mi][ni][3] + bb.y);
            if (RESID) {
                float2 ra = *(const float2*)(R + (size_t)row * N + col);
                float2 rb = *(const float2*)(R + (size_t)(row + 8) * N + col);
                v0.x += ra.x; v0.y += ra.y; v1.x += rb.x; v1.y += rb.y;
            }
            if (ROUND) {
                v0.x = rtf32(v0.x); v0.y = rtf32(v0.y);
                v1.x = rtf32(v1.x); v1.y = rtf32(v1.y);
            }
            *(float2*)(C + (size_t)row * N + col)       = v0;
            *(float2*)(C + (size_t)(row + 8) * N + col) = v1;
        }
    }
}

// ---------------------------------------------------------------------------
// Windowed attention on tensor cores + ldmatrix for Q/P/K fragments.
// ---------------------------------------------------------------------------
#define APAD 68
#define ATTN_SMEM (3*64*APAD*4)

__global__ void __launch_bounds__(128) attn_mma(const float* __restrict__ qkv,
                                                float* __restrict__ out)
{
    extern __shared__ float smf[];
    float* Qs = smf;                 // 64 x 68 (rows reused for P per-warp)
    float* Ks = smf +     64 * APAD;
    float* Vs = smf + 2 * 64 * APAD;
    const int tid  = threadIdx.x;
    const int wid  = tid >> 5, lane = tid & 31;
    const int g    = lane >> 2, tg = lane & 3;
    const int m0   = wid << 4;
    const size_t base = ((size_t)(blockIdx.z * L_ + blockIdx.x * W_)) * (3 * D_)
                        + blockIdx.y * HD_;

    const uint32_t Qb = smem_u32(Qs);
    const uint32_t Kb = smem_u32(Ks);

    // ldmatrix per-lane offsets
    const int lrA = lane & 15;
    const int lcA = (lane >> 4) << 2;
    const uint32_t qoff = (uint32_t)(((m0 + lrA) * APAD + lcA) << 2);
    const int lrB = ((lane >> 4) << 3) + (lane & 7);
    const int lcB = ((lane >> 3) & 1) << 2;
    uint32_t koff[4];
#pragma unroll
    for (int p = 0; p < 4; p++)
        koff[p] = (uint32_t)((((p << 4) + lrB) * APAD + lcB) << 2);

    for (int i = tid; i < 64 * 16; i += 128) {
        const int r = i >> 4, c = (i & 15) << 2;
        const float* p = qkv + base + (size_t)r * (3 * D_) + c;
        *(float4*)(Qs + r * APAD + c) = *(const float4*)(p);
        *(float4*)(Ks + r * APAD + c) = *(const float4*)(p + D_);
        *(float4*)(Vs + r * APAD + c) = *(const float4*)(p + 2 * D_);
    }
    __syncthreads();

    // S = Q K^T
    float s[8][4];
#pragma unroll
    for (int t = 0; t < 8; t++)
#pragma unroll
        for (int i = 0; i < 4; i++) s[t][i] = 0.f;

#pragma unroll
    for (int ks = 0; ks < 8; ks++) {
        const uint32_t kb = (uint32_t)(ks << 5);
        uint32_t a[4], bfr[8][2];
        ldsm4(a, Qb + qoff + kb);
#pragma unroll
        for (int p = 0; p < 4; p++) {
            uint32_t t4[4];
            ldsm4(t4, Kb + koff[p] + kb);
            bfr[2*p][0]   = t4[0]; bfr[2*p][1]   = t4[1];
            bfr[2*p+1][0] = t4[2]; bfr[2*p+1][1] = t4[3];
        }
#pragma unroll
        for (int t = 0; t < 8; t++)
            mma_16x8x8_tf32(s[t], a, bfr[t]);
    }

    // softmax over 64 cols; rows g (c0,c1) and g+8 (c2,c3)
    float mxl = -3.0e38f, mxh = -3.0e38f;
#pragma unroll
    for (int t = 0; t < 8; t++) {
#pragma unroll
        for (int i = 0; i < 4; i++) s[t][i] *= 0.125f;
        mxl = fmaxf(mxl, fmaxf(s[t][0], s[t][1]));
        mxh = fmaxf(mxh, fmaxf(s[t][2], s[t][3]));
    }
    mxl = fmaxf(mxl, __shfl_xor_sync(0xffffffffu, mxl, 1));
    mxl = fmaxf(mxl, __shfl_xor_sync(0xffffffffu, mxl, 2));
    mxh = fmaxf(mxh, __shfl_xor_sync(0xffffffffu, mxh, 1));
    mxh = fmaxf(mxh, __shfl_xor_sync(0xffffffffu, mxh, 2));

    float sl = 0.f, sh = 0.f;
#pragma unroll
    for (int t = 0; t < 8; t++) {
        s[t][0] = __expf(s[t][0] - mxl); sl += s[t][0];
        s[t][1] = __expf(s[t][1] - mxl); sl += s[t][1];
        s[t][2] = __expf(s[t][2] - mxh); sh += s[t][2];
        s[t][3] = __expf(s[t][3] - mxh); sh += s[t][3];
    }
    sl += __shfl_xor_sync(0xffffffffu, sl, 1);
    sl += __shfl_xor_sync(0xffffffffu, sl, 2);
    sh += __shfl_xor_sync(0xffffffffu, sh, 1);
    sh += __shfl_xor_sync(0xffffffffu, sh, 2);
    const float il = 1.0f / sl, ih = 1.0f / sh;

#pragma unroll
    for (int t = 0; t < 8; t++) {
        const int cc = (t << 3) + (tg << 1);
        *(float2*)(Qs + (m0 + g) * APAD + cc) =
            make_float2(rtf32(s[t][0] * il), rtf32(s[t][1] * il));
        *(float2*)(Qs + (m0 + g + 8) * APAD + cc) =
            make_float2(rtf32(s[t][2] * ih), rtf32(s[t][3] * ih));
    }
    __syncwarp();

    // O = P V
    float o[8][4];
#pragma unroll
    for (int t = 0; t < 8; t++)
#pragma unroll
        for (int i = 0; i < 4; i++) o[t][i] = 0.f;

#pragma unroll
    for (int ks = 0; ks < 8; ks++) {
        const int ko = ks << 3;
        uint32_t a[4];
        ldsm4(a, Qb + qoff + (uint32_t)(ko << 2));
#pragma unroll
        for (int t = 0; t < 8; t++) {
            uint32_t b[2];
            b[0] = __float_as_uint(Vs[(ko + tg) * APAD + (t << 3) + g]);
            b[1] = __float_as_uint(Vs[(ko + tg + 4) * APAD + (t << 3) + g]);
            mma_16x8x8_tf32(o[t], a, b);
        }
    }

    const size_t row = (size_t)(blockIdx.z * L_ + blockIdx.x * W_ + m0 + g);
    const int colb = blockIdx.y * HD_;
#pragma unroll
    for (int t = 0; t < 8; t++) {
        const int cc = colb + (t << 3) + (tg << 1);
        *(float2*)(out + row * D_ + cc) =
            make_float2(rtf32(o[t][0]), rtf32(o[t][1]));
        *(float2*)(out + (row + 8) * D_ + cc) =
            make_float2(rtf32(o[t][2]), rtf32(o[t][3]));
    }
}

// ---------------------------------------------------------------------------
// LayerNorm: one block per row of 1024.
// ---------------------------------------------------------------------------
__global__ void __launch_bounds__(256) ln_kernel(const float* __restrict__ y,
                                                 const float* __restrict__ gamma,
                                                 const float* __restrict__ beta,
                                                 float* __restrict__ out)
{
    __shared__ float red[8];
    const int row = blockIdx.x, tid = threadIdx.x;
    const float* yr = y + (size_t)row * D_;
    float4 v = *(const float4*)(yr + (tid << 2));

    float sAcc = v.x + v.y + v.z + v.w;
#pragma unroll
    for (int o = 16; o > 0; o >>= 1) sAcc += __shfl_xor_sync(0xffffffffu, sAcc, o);
    if ((tid & 31) == 0) red[tid >> 5] = sAcc;
    __syncthreads();
    float tot = 0.f;
#pragma unroll
    for (int i = 0; i < 8; i++) tot += red[i];
    const float mean = tot * (1.0f / 1024.0f);

    const float dx = v.x - mean, dy = v.y - mean, dz = v.z - mean, dw = v.w - mean;
    float s2 = dx * dx + dy * dy + dz * dz + dw * dw;
#pragma unroll
    for (int o = 16; o > 0; o >>= 1) s2 += __shfl_xor_sync(0xffffffffu, s2, o);
    __syncthreads();
    if ((tid & 31) == 0) red[tid >> 5] = s2;
    __syncthreads();
    float tot2 = 0.f;
#pragma unroll
    for (int i = 0; i < 8; i++) tot2 += red[i];
    const float rstd = rsqrtf(tot2 * (1.0f / 1024.0f) + EPS_);

    float4 gm = *(const float4*)(gamma + (tid << 2));
    float4 be = *(const float4*)(beta  + (tid << 2));
    float4 o4 = make_float4(dx * rstd * gm.x + be.x,
                            dy * rstd * gm.y + be.y,
                            dz * rstd * gm.z + be.z,
                            dw * rstd * gm.w + be.w);
    *(float4*)(out + (size_t)row * D_ + (tid << 2)) = o4;
}

// ---------------------------------------------------------------------------
extern "C" void kernel_launch(void* const* d_in, const int* in_sizes, int n_in,
                              void* d_out, int out_size)
{
    const float* x     = (const float*)d_in[0];
    const float* Wqkv  = (const float*)d_in[1];
    const float* bqkv  = (const float*)d_in[2];
    const float* Wproj = (const float*)d_in[3];
    const float* bproj = (const float*)d_in[4];
    const float* gamma = (const float*)d_in[5];
    const float* beta  = (const float*)d_in[6];
    float* out = (float*)d_out;

    float *qkv, *attn, *y, *xr, *wq, *wp;
    cudaGetSymbolAddress((void**)&qkv,  g_qkv);
    cudaGetSymbolAddress((void**)&attn, g_attn);
    cudaGetSymbolAddress((void**)&y,    g_y);
    cudaGetSymbolAddress((void**)&xr,   g_xr);
    cudaGetSymbolAddress((void**)&wq,   g_wq);
    cudaGetSymbolAddress((void**)&wp,   g_wp);

    cudaFuncSetAttribute(gemm_mma<0,1>, cudaFuncAttributeMaxDynamicSharedMemorySize, GEMM_SMEM);
    cudaFuncSetAttribute(gemm_mma<1,0>, cudaFuncAttributeMaxDynamicSharedMemorySize, GEMM_SMEM);
    cudaFuncSetAttribute(attn_mma, cudaFuncAttributeMaxDynamicSharedMemorySize, ATTN_SMEM);

    // 0) round GEMM operands to tf32 once
    round_tf32<<<(ML_*D_/4 + 255)/256, 256>>>(x,     xr, ML_*D_/4);
    round_tf32<<<(3*D_*D_/4 + 255)/256, 256>>>(Wqkv, wq, 3*D_*D_/4);
    round_tf32<<<(D_*D_/4 + 255)/256, 256>>>(Wproj,  wp, D_*D_/4);

    // 1) QKV projection (epilogue rounds Q,K,V for the attention MMA)
    gemm_mma<0,1><<<dim3(24, 128), 256, GEMM_SMEM>>>(xr, wq, bqkv, xr, qkv,
                                                     ML_, 3 * D_, D_);
    // 2) windowed attention on tensor cores
    attn_mma<<<dim3(64, 16, 4), 128, ATTN_SMEM>>>(qkv, attn);
    // 3) output projection + bias + residual (residual = original x)
    gemm_mma<1,0><<<dim3(8, 128), 256, GEMM_SMEM>>>(attn, wp, bproj, x, y,
                                                    ML_, D_, D_);
    // 4) layernorm
    ln_kernel<<<ML_, 256>>>(y, gamma, beta, out);
}

// round 10
// speedup vs baseline: 1.6097x; 1.6097x over previous
#include <cuda_runtime.h>
#include <cstdint>

#define B_ 4
#define L_ 4096
#define D_ 1024
#define H_ 16
#define W_ 64
#define HD_ 64
#define ML_ (B_*L_)      // 16384 rows
#define EPS_ 1e-5f

// Scratch (allocation-free rule: __device__ globals)
__device__ float g_qkv [(size_t)ML_ * 3 * D_];   // [B*L, 3*D] (tf32-rounded)
__device__ float g_attn[(size_t)ML_ * D_];       // [B*L, D]   (tf32-rounded)
__device__ float g_y   [(size_t)ML_ * D_];       // pre-LN residual sum
__device__ float g_xr  [(size_t)ML_ * D_];       // x rounded to tf32
__device__ float g_wq  [(size_t)3 * D_ * D_];    // Wqkv rounded
__device__ float g_wp  [(size_t)D_ * D_];        // Wproj rounded

// ---------------------------------------------------------------------------
__device__ __forceinline__ uint32_t f2tf32(float f) {
    uint32_t u;
    asm("cvt.rna.tf32.f32 %0, %1;" : "=r"(u) : "f"(f));
    return u;
}
__device__ __forceinline__ float rtf32(float f) {
    return __uint_as_float(f2tf32(f));
}
__device__ __forceinline__ uint32_t smem_u32(const void* p) {
    uint32_t a;
    asm("{ .reg .u64 t; cvta.to.shared.u64 t, %1; cvt.u32.u64 %0, t; }"
        : "=r"(a) : "l"(p));
    return a;
}
__device__ __forceinline__ void cp16(uint32_t dst, const void* src) {
    asm volatile("cp.async.cg.shared.global [%0], [%1], 16;"
                 :: "r"(dst), "l"(src) : "memory");
}
__device__ __forceinline__ void mma_16x8x8_tf32(float* c, const uint32_t* a,
                                                const uint32_t* b) {
    asm volatile(
        "mma.sync.aligned.m16n8k8.row.col.f32.tf32.tf32.f32 "
        "{%0,%1,%2,%3}, {%4,%5,%6,%7}, {%8,%9}, {%0,%1,%2,%3};"
        : "+f"(c[0]), "+f"(c[1]), "+f"(c[2]), "+f"(c[3])
        : "r"(a[0]), "r"(a[1]), "r"(a[2]), "r"(a[3]), "r"(b[0]), "r"(b[1]));
}
// ldmatrix x4 b16: viewed as b32, r_i[lane l] = tile_i[l>>2][l&3] where
// tile_i is addressed by lanes 8i..8i+7 (lane j -> row j of the 8x(16B) tile).
__device__ __forceinline__ void ldsm4(uint32_t* r, uint32_t addr) {
    asm volatile("ldmatrix.sync.aligned.m8n8.x4.shared.b16 {%0,%1,%2,%3}, [%4];"
                 : "=r"(r[0]), "=r"(r[1]), "=r"(r[2]), "=r"(r[3]) : "r"(addr));
}

// ---------------------------------------------------------------------------
// Fused tf32 rounding prepass: one launch covers xr, wq, wp.
// n4 totals: x 4194304/4, wq 3145728/4, wp 1048576/4 (in float4 units)
// ---------------------------------------------------------------------------
#define N4_X  (ML_*D_/4)
#define N4_WQ (3*D_*D_/4)
#define N4_WP (D_*D_/4)

__global__ void round_tf32_all(const float* __restrict__ x,
                               const float* __restrict__ Wqkv,
                               const float* __restrict__ Wproj,
                               float* __restrict__ xr,
                               float* __restrict__ wq,
                               float* __restrict__ wp)
{
    int i = blockIdx.x * blockDim.x + threadIdx.x;
    const float4* src;
    float4* dst;
    int j;
    if (i < N4_X)                  { src = (const float4*)x;     dst = (float4*)xr; j = i; }
    else if (i < N4_X + N4_WQ)     { src = (const float4*)Wqkv;  dst = (float4*)wq; j = i - N4_X; }
    else if (i < N4_X + N4_WQ + N4_WP) { src = (const float4*)Wproj; dst = (float4*)wp; j = i - N4_X - N4_WQ; }
    else return;
    float4 v = src[j];
    v.x = rtf32(v.x); v.y = rtf32(v.y); v.z = rtf32(v.z); v.w = rtf32(v.w);
    dst[j] = v;
}

// ---------------------------------------------------------------------------
// Tensor-core GEMM via mma.sync + cp.async + ldmatrix.
// CTA 128x128, K-tile 32, 3-stage cp.async, 2 CTAs/SM, A-fragment pipeline.
// (round-8 configuration: A double-buffered, B just-in-time — register-feasible)
// ---------------------------------------------------------------------------
#define TS 36
#define BUFW (128*TS*2)          // words per stage (A then B)
#define GEMM_SMEM (3*BUFW*4)     // 110592 B

template<int RESID, int ROUND>
__global__ void __launch_bounds__(256, 2) gemm_mma(
    const float* __restrict__ A, const float* __restrict__ Bw,
    const float* __restrict__ bias, const float* __restrict__ R,
    float* __restrict__ C, int M, int N, int K)
{
    extern __shared__ float sm[];
    const uint32_t sbase = smem_u32(sm);
    const int tid  = threadIdx.x;
    const int wid  = tid >> 5, lane = tid & 31;
    const int g    = lane >> 2, tg = lane & 3;
    const int wm   = (wid >> 2) << 6;
    const int wn   = (wid & 3) << 5;
    const int bm   = blockIdx.y << 7, bn = blockIdx.x << 7;
    const int r0   = tid >> 3, c0 = (tid & 7) << 2;
    const int ntk  = K >> 5;

    // ldmatrix per-lane byte offsets (within a stage buffer)
    const int lrA = lane & 15;                  // row-within-16
    const int lcA = (lane >> 4) << 2;           // col 0 or 4 (words)
    uint32_t aoff[2];
#pragma unroll
    for (int mh = 0; mh < 2; mh++)
        aoff[mh] = (uint32_t)(((wm + (mh << 4) + lrA) * TS + lcA) << 2);
    const int lrB = ((lane >> 4) << 3) + (lane & 7);
    const int lcB = ((lane >> 3) & 1) << 2;
    uint32_t boff[2];
#pragma unroll
    for (int p = 0; p < 2; p++)
        boff[p] = (uint32_t)(((wn + (p << 4) + lrB) * TS + lcB) << 2);

    float acc[4][4][4];
#pragma unroll
    for (int mi = 0; mi < 4; mi++)
#pragma unroll
        for (int ni = 0; ni < 4; ni++)
#pragma unroll
            for (int i = 0; i < 4; i++) acc[mi][ni][i] = 0.f;

    auto cp_tile = [&](int kt, int buf) {
        const int kc = kt << 5;
        const uint32_t da = sbase + (uint32_t)((buf * BUFW + r0 * TS + c0) << 2);
        const uint32_t db = da + (uint32_t)((128 * TS) << 2);
#pragma unroll
        for (int i = 0; i < 4; i++) {
            cp16(da + (uint32_t)((i << 5) * TS << 2),
                 A  + (size_t)(bm + r0 + (i << 5)) * K + kc + c0);
            cp16(db + (uint32_t)((i << 5) * TS << 2),
                 Bw + (size_t)(bn + r0 + (i << 5)) * K + kc + c0);
        }
        asm volatile("cp.async.commit_group;" ::: "memory");
    };

    cp_tile(0, 0);
    if (ntk > 1) cp_tile(1, 1);

    int buf = 0;
    for (int kt = 0; kt < ntk; kt++) {
        if (kt < ntk - 1)
            asm volatile("cp.async.wait_group 1;" ::: "memory");
        else
            asm volatile("cp.async.wait_group 0;" ::: "memory");
        __syncthreads();

        const uint32_t Ab = sbase + (uint32_t)((buf * BUFW) << 2);
        const uint32_t Bb = Ab + (uint32_t)((128 * TS) << 2);

        // A-fragment software pipeline: load ks=0, then prefetch ks+1
        uint32_t afb[2][4][4];
#pragma unroll
        for (int mi = 0; mi < 4; mi++)
            ldsm4(afb[0][mi], Ab + aoff[mi & 1]
                          + (uint32_t)((mi >> 1) * ((TS << 5) << 2)));

#pragma unroll
        for (int ks = 0; ks < 4; ks++) {
            const uint32_t kb = (uint32_t)(ks << 5);   // ko*4 bytes
            uint32_t bf[4][2];
#pragma unroll
            for (int p = 0; p < 2; p++) {
                uint32_t t4[4];
                ldsm4(t4, Bb + boff[p] + kb);
                bf[2*p][0]   = t4[0]; bf[2*p][1]   = t4[1];
                bf[2*p+1][0] = t4[2]; bf[2*p+1][1] = t4[3];
            }
            if (ks < 3) {
                const uint32_t kb2 = (uint32_t)((ks + 1) << 5);
#pragma unroll
                for (int mi = 0; mi < 4; mi++)
                    ldsm4(afb[(ks + 1) & 1][mi], Ab + aoff[mi & 1]
                                  + (uint32_t)((mi >> 1) * ((TS << 5) << 2)) + kb2);
            }
#pragma unroll
            for (int ni = 0; ni < 4; ni++)
#pragma unroll
                for (int mi = 0; mi < 4; mi++)
                    mma_16x8x8_tf32(acc[mi][ni], afb[ks & 1][mi], bf[ni]);

            // issue next-stage cp.async after first MMA batch (tensor pipe hot)
            if (ks == 0 && kt + 2 < ntk) {
                int nb = buf + 2; if (nb >= 3) nb -= 3;
                cp_tile(kt + 2, nb);
            }
        }
        if (++buf == 3) buf = 0;
    }

#pragma unroll
    for (int mi = 0; mi < 4; mi++) {
#pragma unroll
        for (int ni = 0; ni < 4; ni++) {
            const int row = bm + wm + (mi << 4) + g;
            const int col = bn + wn + (ni << 3) + (tg << 1);
            float2 bb = *(const float2*)(bias + col);
            float2 v0 = make_float2(acc[mi][ni][0] + bb.x, acc[mi][ni][1] + bb.y);
            float2 v1 = make_float2(acc[mi][ni][2] + bb.x, acc[mi][ni][3] + bb.y);
            if (RESID) {
                float2 ra = *(const float2*)(R + (size_t)row * N + col);
                float2 rb = *(const float2*)(R + (size_t)(row + 8) * N + col);
                v0.x += ra.x; v0.y += ra.y; v1.x += rb.x; v1.y += rb.y;
            }
            if (ROUND) {
                v0.x = rtf32(v0.x); v0.y = rtf32(v0.y);
                v1.x = rtf32(v1.x); v1.y = rtf32(v1.y);
            }
            *(float2*)(C + (size_t)row * N + col)       = v0;
            *(float2*)(C + (size_t)(row + 8) * N + col) = v1;
        }
    }
}

// ---------------------------------------------------------------------------
// Windowed attention on tensor cores + ldmatrix for Q/P/K fragments.
// ---------------------------------------------------------------------------
#define APAD 68
#define ATTN_SMEM (3*64*APAD*4)

__global__ void __launch_bounds__(128) attn_mma(const float* __restrict__ qkv,
                                                float* __restrict__ out)
{
    extern __shared__ float smf[];
    float* Qs = smf;                 // 64 x 68 (rows reused for P per-warp)
    float* Ks = smf +     64 * APAD;
    float* Vs = smf + 2 * 64 * APAD;
    const int tid  = threadIdx.x;
    const int wid  = tid >> 5, lane = tid & 31;
    const int g    = lane >> 2, tg = lane & 3;
    const int m0   = wid << 4;
    const size_t base = ((size_t)(blockIdx.z * L_ + blockIdx.x * W_)) * (3 * D_)
                        + blockIdx.y * HD_;

    const uint32_t Qb = smem_u32(Qs);
    const uint32_t Kb = smem_u32(Ks);

    // ldmatrix per-lane offsets
    const int lrA = lane & 15;
    const int lcA = (lane >> 4) << 2;
    const uint32_t qoff = (uint32_t)(((m0 + lrA) * APAD + lcA) << 2);
    const int lrB = ((lane >> 4) << 3) + (lane & 7);
    const int lcB = ((lane >> 3) & 1) << 2;
    uint32_t koff[4];
#pragma unroll
    for (int p = 0; p < 4; p++)
        koff[p] = (uint32_t)((((p << 4) + lrB) * APAD + lcB) << 2);

    for (int i = tid; i < 64 * 16; i += 128) {
        const int r = i >> 4, c = (i & 15) << 2;
        const float* p = qkv + base + (size_t)r * (3 * D_) + c;
        *(float4*)(Qs + r * APAD + c) = *(const float4*)(p);
        *(float4*)(Ks + r * APAD + c) = *(const float4*)(p + D_);
        *(float4*)(Vs + r * APAD + c) = *(const float4*)(p + 2 * D_);
    }
    __syncthreads();

    // S = Q K^T
    float s[8][4];
#pragma unroll
    for (int t = 0; t < 8; t++)
#pragma unroll
        for (int i = 0; i < 4; i++) s[t][i] = 0.f;

#pragma unroll
    for (int ks = 0; ks < 8; ks++) {
        const uint32_t kb = (uint32_t)(ks << 5);
        uint32_t a[4], bfr[8][2];
        ldsm4(a, Qb + qoff + kb);
#pragma unroll
        for (int p = 0; p < 4; p++) {
            uint32_t t4[4];
            ldsm4(t4, Kb + koff[p] + kb);
            bfr[2*p][0]   = t4[0]; bfr[2*p][1]   = t4[1];
            bfr[2*p+1][0] = t4[2]; bfr[2*p+1][1] = t4[3];
        }
#pragma unroll
        for (int t = 0; t < 8; t++)
            mma_16x8x8_tf32(s[t], a, bfr[t]);
    }

    // softmax over 64 cols; rows g (c0,c1) and g+8 (c2,c3)
    float mxl = -3.0e38f, mxh = -3.0e38f;
#pragma unroll
    for (int t = 0; t < 8; t++) {
#pragma unroll
        for (int i = 0; i < 4; i++) s[t][i] *= 0.125f;
        mxl = fmaxf(mxl, fmaxf(s[t][0], s[t][1]));
        mxh = fmaxf(mxh, fmaxf(s[t][2], s[t][3]));
    }
    mxl = fmaxf(mxl, __shfl_xor_sync(0xffffffffu, mxl, 1));
    mxl = fmaxf(mxl, __shfl_xor_sync(0xffffffffu, mxl, 2));
    mxh = fmaxf(mxh, __shfl_xor_sync(0xffffffffu, mxh, 1));
    mxh = fmaxf(mxh, __shfl_xor_sync(0xffffffffu, mxh, 2));

    float sl = 0.f, sh = 0.f;
#pragma unroll
    for (int t = 0; t < 8; t++) {
        s[t][0] = __expf(s[t][0] - mxl); sl += s[t][0];
        s[t][1] = __expf(s[t][1] - mxl); sl += s[t][1];
        s[t][2] = __expf(s[t][2] - mxh); sh += s[t][2];
        s[t][3] = __expf(s[t][3] - mxh); sh += s[t][3];
    }
    sl += __shfl_xor_sync(0xffffffffu, sl, 1);
    sl += __shfl_xor_sync(0xffffffffu, sl, 2);
    sh += __shfl_xor_sync(0xffffffffu, sh, 1);
    sh += __shfl_xor_sync(0xffffffffu, sh, 2);
    const float il = 1.0f / sl, ih = 1.0f / sh;

#pragma unroll
    for (int t = 0; t < 8; t++) {
        const int cc = (t << 3) + (tg << 1);
        *(float2*)(Qs + (m0 + g) * APAD + cc) =
            make_float2(rtf32(s[t][0] * il), rtf32(s[t][1] * il));
        *(float2*)(Qs + (m0 + g + 8) * APAD + cc) =
            make_float2(rtf32(s[t][2] * ih), rtf32(s[t][3] * ih));
    }
    __syncwarp();

    // O = P V
    float o[8][4];
#pragma unroll
    for (int t = 0; t < 8; t++)
#pragma unroll
        for (int i = 0; i < 4; i++) o[t][i] = 0.f;

#pragma unroll
    for (int ks = 0; ks < 8; ks++) {
        const int ko = ks << 3;
        uint32_t a[4];
        ldsm4(a, Qb + qoff + (uint32_t)(ko << 2));
#pragma unroll
        for (int t = 0; t < 8; t++) {
            uint32_t b[2];
            b[0] = __float_as_uint(Vs[(ko + tg) * APAD + (t << 3) + g]);
            b[1] = __float_as_uint(Vs[(ko + tg + 4) * APAD + (t << 3) + g]);
            mma_16x8x8_tf32(o[t], a, b);
        }
    }

    const size_t row = (size_t)(blockIdx.z * L_ + blockIdx.x * W_ + m0 + g);
    const int colb = blockIdx.y * HD_;
#pragma unroll
    for (int t = 0; t < 8; t++) {
        const int cc = colb + (t << 3) + (tg << 1);
        *(float2*)(out + row * D_ + cc) =
            make_float2(rtf32(o[t][0]), rtf32(o[t][1]));
        *(float2*)(out + (row + 8) * D_ + cc) =
            make_float2(rtf32(o[t][2]), rtf32(o[t][3]));
    }
}

// ---------------------------------------------------------------------------
// LayerNorm: one block per 2 rows of 1024.
// ---------------------------------------------------------------------------
__global__ void __launch_bounds__(256) ln_kernel(const float* __restrict__ y,
                                                 const float* __restrict__ gamma,
                                                 const float* __restrict__ beta,
                                                 float* __restrict__ out)
{
    __shared__ float red[8];
    const int tid = threadIdx.x;
    float4 gm = *(const float4*)(gamma + (tid << 2));
    float4 be = *(const float4*)(beta  + (tid << 2));

#pragma unroll
    for (int rr = 0; rr < 2; rr++) {
        const int row = (blockIdx.x << 1) + rr;
        const float* yr = y + (size_t)row * D_;
        float4 v = *(const float4*)(yr + (tid << 2));

        float sAcc = v.x + v.y + v.z + v.w;
#pragma unroll
        for (int o = 16; o > 0; o >>= 1) sAcc += __shfl_xor_sync(0xffffffffu, sAcc, o);
        if ((tid & 31) == 0) red[tid >> 5] = sAcc;
        __syncthreads();
        float tot = 0.f;
#pragma unroll
        for (int i = 0; i < 8; i++) tot += red[i];
        const float mean = tot * (1.0f / 1024.0f);

        const float dx = v.x - mean, dy = v.y - mean, dz = v.z - mean, dw = v.w - mean;
        float s2 = dx * dx + dy * dy + dz * dz + dw * dw;
#pragma unroll
        for (int o = 16; o > 0; o >>= 1) s2 += __shfl_xor_sync(0xffffffffu, s2, o);
        __syncthreads();
        if ((tid & 31) == 0) red[tid >> 5] = s2;
        __syncthreads();
        float tot2 = 0.f;
#pragma unroll
        for (int i = 0; i < 8; i++) tot2 += red[i];
        const float rstd = rsqrtf(tot2 * (1.0f / 1024.0f) + EPS_);

        float4 o4 = make_float4(dx * rstd * gm.x + be.x,
                                dy * rstd * gm.y + be.y,
                                dz * rstd * gm.z + be.z,
                                dw * rstd * gm.w + be.w);
        *(float4*)(out + (size_t)row * D_ + (tid << 2)) = o4;
        if (rr == 0) __syncthreads();
    }
}

// ---------------------------------------------------------------------------
extern "C" void kernel_launch(void* const* d_in, const int* in_sizes, int n_in,
                              void* d_out, int out_size)
{
    const float* x     = (const float*)d_in[0];
    const float* Wqkv  = (const float*)d_in[1];
    const float* bqkv  = (const float*)d_in[2];
    const float* Wproj = (const float*)d_in[3];
    const float* bproj = (const float*)d_in[4];
    const float* gamma = (const float*)d_in[5];
    const float* beta  = (const float*)d_in[6];
    float* out = (float*)d_out;

    float *qkv, *attn, *y, *xr, *wq, *wp;
    cudaGetSymbolAddress((void**)&qkv,  g_qkv);
    cudaGetSymbolAddress((void**)&attn, g_attn);
    cudaGetSymbolAddress((void**)&y,    g_y);
    cudaGetSymbolAddress((void**)&xr,   g_xr);
    cudaGetSymbolAddress((void**)&wq,   g_wq);
    cudaGetSymbolAddress((void**)&wp,   g_wp);

    cudaFuncSetAttribute(gemm_mma<0,1>, cudaFuncAttributeMaxDynamicSharedMemorySize, GEMM_SMEM);
    cudaFuncSetAttribute(gemm_mma<1,0>, cudaFuncAttributeMaxDynamicSharedMemorySize, GEMM_SMEM);
    cudaFuncSetAttribute(attn_mma, cudaFuncAttributeMaxDynamicSharedMemorySize, ATTN_SMEM);

    // 0) round all GEMM operands to tf32 in one launch
    const int n4_all = N4_X + N4_WQ + N4_WP;
    round_tf32_all<<<(n4_all + 255) / 256, 256>>>(x, Wqkv, Wproj, xr, wq, wp);

    // 1) QKV projection (epilogue rounds Q,K,V for the attention MMA)
    gemm_mma<0,1><<<dim3(24, 128), 256, GEMM_SMEM>>>(xr, wq, bqkv, xr, qkv,
                                                     ML_, 3 * D_, D_);
    // 2) windowed attention on tensor cores
    attn_mma<<<dim3(64, 16, 4), 128, ATTN_SMEM>>>(qkv, attn);
    // 3) output projection + bias + residual (residual = original x)
    gemm_mma<1,0><<<dim3(8, 128), 256, GEMM_SMEM>>>(attn, wp, bproj, x, y,
                                                    ML_, D_, D_);
    // 4) layernorm (2 rows per block)
    ln_kernel<<<ML_/2, 256>>>(y, gamma, beta, out);
}

// round 11
// speedup vs baseline: 2.8466x; 1.7684x over previous
#include <cuda_runtime.h>
#include <cuda_fp16.h>
#include <cstdint>

#define B_ 4
#define L_ 4096
#define D_ 1024
#define H_ 16
#define W_ 64
#define HD_ 64
#define ML_ (B_*L_)      // 16384 rows
#define EPS_ 1e-5f

// Scratch (allocation-free rule: __device__ globals)
__device__ __half g_qkvh[(size_t)ML_ * 3 * D_]; // [B*L, 3*D] fp16
__device__ __half g_attnh[(size_t)ML_ * D_];    // [B*L, D]   fp16
__device__ float  g_y  [(size_t)ML_ * D_];      // pre-LN residual sum (fp32)
__device__ __half g_xh [(size_t)ML_ * D_];      // x in fp16
__device__ __half g_wqh[(size_t)3 * D_ * D_];   // Wqkv fp16
__device__ __half g_wph[(size_t)D_ * D_];       // Wproj fp16

// ---------------------------------------------------------------------------
__device__ __forceinline__ uint32_t smem_u32(const void* p) {
    uint32_t a;
    asm("{ .reg .u64 t; cvta.to.shared.u64 t, %1; cvt.u32.u64 %0, t; }"
        : "=r"(a) : "l"(p));
    return a;
}
__device__ __forceinline__ void cp16(uint32_t dst, const void* src) {
    asm volatile("cp.async.cg.shared.global [%0], [%1], 16;"
                 :: "r"(dst), "l"(src) : "memory");
}
__device__ __forceinline__ void mma_16x8x16_f16(float* c, const uint32_t* a,
                                                const uint32_t* b) {
    asm volatile(
        "mma.sync.aligned.m16n8k16.row.col.f32.f16.f16.f32 "
        "{%0,%1,%2,%3}, {%4,%5,%6,%7}, {%8,%9}, {%0,%1,%2,%3};"
        : "+f"(c[0]), "+f"(c[1]), "+f"(c[2]), "+f"(c[3])
        : "r"(a[0]), "r"(a[1]), "r"(a[2]), "r"(a[3]), "r"(b[0]), "r"(b[1]));
}
__device__ __forceinline__ void ldsm4(uint32_t* r, uint32_t addr) {
    asm volatile("ldmatrix.sync.aligned.m8n8.x4.shared.b16 {%0,%1,%2,%3}, [%4];"
                 : "=r"(r[0]), "=r"(r[1]), "=r"(r[2]), "=r"(r[3]) : "r"(addr));
}
__device__ __forceinline__ void ldsm4t(uint32_t* r, uint32_t addr) {
    asm volatile("ldmatrix.sync.aligned.m8n8.x4.trans.shared.b16 {%0,%1,%2,%3}, [%4];"
                 : "=r"(r[0]), "=r"(r[1]), "=r"(r[2]), "=r"(r[3]) : "r"(addr));
}

// ---------------------------------------------------------------------------
// Fused fp16 conversion prepass: one launch covers xh, wqh, wph.
// ---------------------------------------------------------------------------
#define N4_X  (ML_*D_/4)
#define N4_WQ (3*D_*D_/4)
#define N4_WP (D_*D_/4)

__global__ void to_half_all(const float* __restrict__ x,
                            const float* __restrict__ Wqkv,
                            const float* __restrict__ Wproj,
                            __half* __restrict__ xh,
                            __half* __restrict__ wq,
                            __half* __restrict__ wp)
{
    int i = blockIdx.x * blockDim.x + threadIdx.x;
    const float4* src;
    __half* dst;
    int j;
    if (i < N4_X)                      { src = (const float4*)x;     dst = xh; j = i; }
    else if (i < N4_X + N4_WQ)         { src = (const float4*)Wqkv;  dst = wq; j = i - N4_X; }
    else if (i < N4_X + N4_WQ + N4_WP) { src = (const float4*)Wproj; dst = wp; j = i - N4_X - N4_WQ; }
    else return;
    float4 v = src[j];
    __half2 h0 = __floats2half2_rn(v.x, v.y);
    __half2 h1 = __floats2half2_rn(v.z, v.w);
    ((uint2*)dst)[j] = make_uint2(*(uint32_t*)&h0, *(uint32_t*)&h1);
}

// ---------------------------------------------------------------------------
// fp16 tensor-core GEMM: C = A @ Bw^T + bias (+R / half-out variants)
// CTA 128x128, K-tile 64 (fp16), 3-stage cp.async, 2 CTAs/SM,
// A-fragment double-buffer (round-8 register-feasible shape).
// ---------------------------------------------------------------------------
#define TS 72                        // halves per smem row (144 B)
#define BUFH (128*TS*2)              // halves per stage (A then B)
#define GEMM_SMEM (3*BUFH*2)         // 110592 B

template<int OUTHALF>
__global__ void __launch_bounds__(256, 2) gemm_mma(
    const __half* __restrict__ A, const __half* __restrict__ Bw,
    const float* __restrict__ bias, const float* __restrict__ R,
    void* __restrict__ Cv, int M, int N, int K)
{
    extern __shared__ __half sm[];
    const uint32_t sbase = smem_u32(sm);
    const int tid  = threadIdx.x;
    const int wid  = tid >> 5, lane = tid & 31;
    const int g    = lane >> 2, tg = lane & 3;
    const int wm   = (wid >> 2) << 6;
    const int wn   = (wid & 3) << 5;
    const int bm   = blockIdx.y << 7, bn = blockIdx.x << 7;
    const int r0   = tid >> 3, c0h = (tid & 7) << 3;
    const int ntk  = K >> 6;                     // K-tiles of 64

    // ldmatrix per-lane byte offsets
    const int lrA = lane & 15;
    const uint32_t aoff = (uint32_t)(((wm + lrA) * TS) << 1)
                        + (uint32_t)(((lane >> 4) & 1) << 4);
    const int lrB = ((lane >> 4) << 3) + (lane & 7);
    const uint32_t boffb = (uint32_t)(((wn + lrB) * TS) << 1)
                         + (uint32_t)(((lane >> 3) & 1) << 4);

    float acc[4][4][4];
#pragma unroll
    for (int mi = 0; mi < 4; mi++)
#pragma unroll
        for (int ni = 0; ni < 4; ni++)
#pragma unroll
            for (int i = 0; i < 4; i++) acc[mi][ni][i] = 0.f;

    auto cp_tile = [&](int kt, int buf) {
        const int kc = kt << 6;
        const uint32_t da = sbase + (uint32_t)((buf * BUFH + r0 * TS + c0h) << 1);
        const uint32_t db = da + (uint32_t)((128 * TS) << 1);
#pragma unroll
        for (int i = 0; i < 4; i++) {
            cp16(da + (uint32_t)(((i << 5) * TS) << 1),
                 A  + (size_t)(bm + r0 + (i << 5)) * K + kc + c0h);
            cp16(db + (uint32_t)(((i << 5) * TS) << 1),
                 Bw + (size_t)(bn + r0 + (i << 5)) * K + kc + c0h);
        }
        asm volatile("cp.async.commit_group;" ::: "memory");
    };

    cp_tile(0, 0);
    if (ntk > 1) cp_tile(1, 1);

    int buf = 0;
    for (int kt = 0; kt < ntk; kt++) {
        if (kt < ntk - 1)
            asm volatile("cp.async.wait_group 1;" ::: "memory");
        else
            asm volatile("cp.async.wait_group 0;" ::: "memory");
        __syncthreads();

        const uint32_t Ab = sbase + (uint32_t)((buf * BUFH) << 1);
        const uint32_t Bb = Ab + (uint32_t)((128 * TS) << 1);

        // A-fragment software pipeline over 4 k16-steps
        uint32_t afb[2][4][4];
#pragma unroll
        for (int mi = 0; mi < 4; mi++)
            ldsm4(afb[0][mi], Ab + aoff + (uint32_t)(mi * ((TS << 4) << 1)));

#pragma unroll
        for (int ks = 0; ks < 4; ks++) {
            const uint32_t kb = (uint32_t)(ks << 5);   // 16 halves = 32 B
            uint32_t bf[4][2];
#pragma unroll
            for (int p = 0; p < 2; p++) {
                uint32_t t4[4];
                ldsm4(t4, Bb + boffb + (uint32_t)(p * ((TS << 4) << 1)) + kb);
                bf[2*p][0]   = t4[0]; bf[2*p][1]   = t4[1];
                bf[2*p+1][0] = t4[2]; bf[2*p+1][1] = t4[3];
            }
            if (ks < 3) {
                const uint32_t kb2 = (uint32_t)((ks + 1) << 5);
#pragma unroll
                for (int mi = 0; mi < 4; mi++)
                    ldsm4(afb[(ks + 1) & 1][mi],
                          Ab + aoff + (uint32_t)(mi * ((TS << 4) << 1)) + kb2);
            }
#pragma unroll
            for (int ni = 0; ni < 4; ni++)
#pragma unroll
                for (int mi = 0; mi < 4; mi++)
                    mma_16x8x16_f16(acc[mi][ni], afb[ks & 1][mi], bf[ni]);

            if (ks == 0 && kt + 2 < ntk) {
                int nb = buf + 2; if (nb >= 3) nb -= 3;
                cp_tile(kt + 2, nb);
            }
        }
        if (++buf == 3) buf = 0;
    }

#pragma unroll
    for (int mi = 0; mi < 4; mi++) {
#pragma unroll
        for (int ni = 0; ni < 4; ni++) {
            const int row = bm + wm + (mi << 4) + g;
            const int col = bn + wn + (ni << 3) + (tg << 1);
            float2 bb = *(const float2*)(bias + col);
            float2 v0 = make_float2(acc[mi][ni][0] + bb.x, acc[mi][ni][1] + bb.y);
            float2 v1 = make_float2(acc[mi][ni][2] + bb.x, acc[mi][ni][3] + bb.y);
            if (OUTHALF) {
                __half* Ch = (__half*)Cv;
                *(__half2*)(Ch + (size_t)row * N + col)       = __floats2half2_rn(v0.x, v0.y);
                *(__half2*)(Ch + (size_t)(row + 8) * N + col) = __floats2half2_rn(v1.x, v1.y);
            } else {
                float* Cf = (float*)Cv;
                float2 ra = *(const float2*)(R + (size_t)row * N + col);
                float2 rb = *(const float2*)(R + (size_t)(row + 8) * N + col);
                v0.x += ra.x; v0.y += ra.y; v1.x += rb.x; v1.y += rb.y;
                *(float2*)(Cf + (size_t)row * N + col)       = v0;
                *(float2*)(Cf + (size_t)(row + 8) * N + col) = v1;
            }
        }
    }
}

// ---------------------------------------------------------------------------
// fp16 windowed attention. 1 block = 1 (window, head, batch); 4 warps.
// S=QK^T and O=PV on m16n8k16; V via ldmatrix.trans.
// ---------------------------------------------------------------------------
#define ATTN_SMEM (3*64*TS*2)

__global__ void __launch_bounds__(128) attn_mma(const __half* __restrict__ qkv,
                                                __half* __restrict__ out)
{
    extern __shared__ __half smh[];
    __half* Qs = smh;                // 64 x TS (rows reused for P per-warp)
    __half* Ks = smh +     64 * TS;
    __half* Vs = smh + 2 * 64 * TS;
    const int tid  = threadIdx.x;
    const int wid  = tid >> 5, lane = tid & 31;
    const int g    = lane >> 2, tg = lane & 3;
    const int m0   = wid << 4;
    const size_t base = ((size_t)(blockIdx.z * L_ + blockIdx.x * W_)) * (3 * D_)
                        + blockIdx.y * HD_;

    const uint32_t Qb = smem_u32(Qs);
    const uint32_t Kb = smem_u32(Ks);
    const uint32_t Vb = smem_u32(Vs);

    // ldmatrix per-lane offsets
    const int lrA = lane & 15;
    const uint32_t qoff = (uint32_t)(((m0 + lrA) * TS) << 1)
                        + (uint32_t)(((lane >> 4) & 1) << 4);
    const int lrB = ((lane >> 4) << 3) + (lane & 7);
    const uint32_t koffb = (uint32_t)((lrB * TS) << 1)
                         + (uint32_t)(((lane >> 3) & 1) << 4);
    // V (trans): krow = ((lane>>3)&1)*8 + (lane&7); ncol byte = (lane>>4)*16
    const uint32_t voffb = (uint32_t)(((((lane >> 3) & 1) * 8 + (lane & 7)) * TS) << 1)
                         + (uint32_t)(((lane >> 4) & 1) << 4);

    // load Q,K,V tiles (64 x 64 halves each), 16B chunks
    for (int i = tid; i < 64 * 8; i += 128) {
        const int r = i >> 3, c = (i & 7) << 3;
        const __half* p = qkv + base + (size_t)r * (3 * D_) + c;
        *(uint4*)(Qs + r * TS + c) = *(const uint4*)(p);
        *(uint4*)(Ks + r * TS + c) = *(const uint4*)(p + D_);
        *(uint4*)(Vs + r * TS + c) = *(const uint4*)(p + 2 * D_);
    }
    __syncthreads();

    // S = Q K^T  (contraction over hd=64: 4 k16-steps)
    float s[8][4];
#pragma unroll
    for (int t = 0; t < 8; t++)
#pragma unroll
        for (int i = 0; i < 4; i++) s[t][i] = 0.f;

#pragma unroll
    for (int ks = 0; ks < 4; ks++) {
        const uint32_t kb = (uint32_t)(ks << 5);
        uint32_t a[4], bfr[8][2];
        ldsm4(a, Qb + qoff + kb);
#pragma unroll
        for (int p = 0; p < 4; p++) {
            uint32_t t4[4];
            ldsm4(t4, Kb + koffb + (uint32_t)(p * ((TS << 4) << 1)) + kb);
            bfr[2*p][0]   = t4[0]; bfr[2*p][1]   = t4[1];
            bfr[2*p+1][0] = t4[2]; bfr[2*p+1][1] = t4[3];
        }
#pragma unroll
        for (int t = 0; t < 8; t++)
            mma_16x8x16_f16(s[t], a, bfr[t]);
    }

    // softmax over 64 cols; rows g (c0,c1) and g+8 (c2,c3)
    float mxl = -3.0e38f, mxh = -3.0e38f;
#pragma unroll
    for (int t = 0; t < 8; t++) {
#pragma unroll
        for (int i = 0; i < 4; i++) s[t][i] *= 0.125f;
        mxl = fmaxf(mxl, fmaxf(s[t][0], s[t][1]));
        mxh = fmaxf(mxh, fmaxf(s[t][2], s[t][3]));
    }
    mxl = fmaxf(mxl, __shfl_xor_sync(0xffffffffu, mxl, 1));
    mxl = fmaxf(mxl, __shfl_xor_sync(0xffffffffu, mxl, 2));
    mxh = fmaxf(mxh, __shfl_xor_sync(0xffffffffu, mxh, 1));
    mxh = fmaxf(mxh, __shfl_xor_sync(0xffffffffu, mxh, 2));

    float sl = 0.f, sh = 0.f;
#pragma unroll
    for (int t = 0; t < 8; t++) {
        s[t][0] = __expf(s[t][0] - mxl); sl += s[t][0];
        s[t][1] = __expf(s[t][1] - mxl); sl += s[t][1];
        s[t][2] = __expf(s[t][2] - mxh); sh += s[t][2];
        s[t][3] = __expf(s[t][3] - mxh); sh += s[t][3];
    }
    sl += __shfl_xor_sync(0xffffffffu, sl, 1);
    sl += __shfl_xor_sync(0xffffffffu, sl, 2);
    sh += __shfl_xor_sync(0xffffffffu, sh, 1);
    sh += __shfl_xor_sync(0xffffffffu, sh, 2);
    const float il = 1.0f / sl, ih = 1.0f / sh;

    // write P (fp16) into this warp's private Q rows
#pragma unroll
    for (int t = 0; t < 8; t++) {
        const int cc = (t << 3) + (tg << 1);
        *(__half2*)(Qs + (m0 + g) * TS + cc) =
            __floats2half2_rn(s[t][0] * il, s[t][1] * il);
        *(__half2*)(Qs + (m0 + g + 8) * TS + cc) =
            __floats2half2_rn(s[t][2] * ih, s[t][3] * ih);
    }
    __syncwarp();

    // O = P V  (contraction over 64 keys: 4 k16-steps, V via trans-ldmatrix)
    float o[8][4];
#pragma unroll
    for (int t = 0; t < 8; t++)
#pragma unroll
        for (int i = 0; i < 4; i++) o[t][i] = 0.f;

#pragma unroll
    for (int ks = 0; ks < 4; ks++) {
        uint32_t a[4];
        ldsm4(a, Qb + qoff + (uint32_t)(ks << 5));
        const uint32_t vkb = (uint32_t)(ks * ((TS << 4) << 1));  // 16 key-rows
#pragma unroll
        for (int p = 0; p < 4; p++) {
            uint32_t t4[4];
            ldsm4t(t4, Vb + voffb + vkb + (uint32_t)(p << 5));   // p*16 hd-cols
            o[2*p][0]   += 0.f;  // keep shape; mma below
            uint32_t b0[2] = { t4[0], t4[1] };
            uint32_t b1[2] = { t4[2], t4[3] };
            mma_16x8x16_f16(o[2*p],   a, b0);
            mma_16x8x16_f16(o[2*p+1], a, b1);
        }
    }

    // store O (fp16: feeds the proj GEMM)
    const size_t row = (size_t)(blockIdx.z * L_ + blockIdx.x * W_ + m0 + g);
    const int colb = blockIdx.y * HD_;
#pragma unroll
    for (int t = 0; t < 8; t++) {
        const int cc = colb + (t << 3) + (tg << 1);
        *(__half2*)(out + row * D_ + cc)       = __floats2half2_rn(o[t][0], o[t][1]);
        *(__half2*)(out + (row + 8) * D_ + cc) = __floats2half2_rn(o[t][2], o[t][3]);
    }
}

// ---------------------------------------------------------------------------
// LayerNorm: one block per 2 rows of 1024.
// ---------------------------------------------------------------------------
__global__ void __launch_bounds__(256) ln_kernel(const float* __restrict__ y,
                                                 const float* __restrict__ gamma,
                                                 const float* __restrict__ beta,
                                                 float* __restrict__ out)
{
    __shared__ float red[8];
    const int tid = threadIdx.x;
    float4 gm = *(const float4*)(gamma + (tid << 2));
    float4 be = *(const float4*)(beta  + (tid << 2));

#pragma unroll
    for (int rr = 0; rr < 2; rr++) {
        const int row = (blockIdx.x << 1) + rr;
        const float* yr = y + (size_t)row * D_;
        float4 v = *(const float4*)(yr + (tid << 2));

        float sAcc = v.x + v.y + v.z + v.w;
#pragma unroll
        for (int o = 16; o > 0; o >>= 1) sAcc += __shfl_xor_sync(0xffffffffu, sAcc, o);
        if ((tid & 31) == 0) red[tid >> 5] = sAcc;
        __syncthreads();
        float tot = 0.f;
#pragma unroll
        for (int i = 0; i < 8; i++) tot += red[i];
        const float mean = tot * (1.0f / 1024.0f);

        const float dx = v.x - mean, dy = v.y - mean, dz = v.z - mean, dw = v.w - mean;
        float s2 = dx * dx + dy * dy + dz * dz + dw * dw;
#pragma unroll
        for (int o = 16; o > 0; o >>= 1) s2 += __shfl_xor_sync(0xffffffffu, s2, o);
        __syncthreads();
        if ((tid & 31) == 0) red[tid >> 5] = s2;
        __syncthreads();
        float tot2 = 0.f;
#pragma unroll
        for (int i = 0; i < 8; i++) tot2 += red[i];
        const float rstd = rsqrtf(tot2 * (1.0f / 1024.0f) + EPS_);

        float4 o4 = make_float4(dx * rstd * gm.x + be.x,
                                dy * rstd * gm.y + be.y,
                                dz * rstd * gm.z + be.z,
                                dw * rstd * gm.w + be.w);
        *(float4*)(out + (size_t)row * D_ + (tid << 2)) = o4;
        if (rr == 0) __syncthreads();
    }
}

// ---------------------------------------------------------------------------
extern "C" void kernel_launch(void* const* d_in, const int* in_sizes, int n_in,
                              void* d_out, int out_size)
{
    const float* x     = (const float*)d_in[0];
    const float* Wqkv  = (const float*)d_in[1];
    const float* bqkv  = (const float*)d_in[2];
    const float* Wproj = (const float*)d_in[3];
    const float* bproj = (const float*)d_in[4];
    const float* gamma = (const float*)d_in[5];
    const float* beta  = (const float*)d_in[6];
    float* out = (float*)d_out;

    __half *qkv, *attn, *xh, *wq, *wp;
    float *y;
    cudaGetSymbolAddress((void**)&qkv,  g_qkvh);
    cudaGetSymbolAddress((void**)&attn, g_attnh);
    cudaGetSymbolAddress((void**)&y,    g_y);
    cudaGetSymbolAddress((void**)&xh,   g_xh);
    cudaGetSymbolAddress((void**)&wq,   g_wqh);
    cudaGetSymbolAddress((void**)&wp,   g_wph);

    cudaFuncSetAttribute(gemm_mma<1>, cudaFuncAttributeMaxDynamicSharedMemorySize, GEMM_SMEM);
    cudaFuncSetAttribute(gemm_mma<0>, cudaFuncAttributeMaxDynamicSharedMemorySize, GEMM_SMEM);
    cudaFuncSetAttribute(attn_mma, cudaFuncAttributeMaxDynamicSharedMemorySize, ATTN_SMEM);

    // 0) convert all GEMM operands to fp16 in one launch
    const int n4_all = N4_X + N4_WQ + N4_WP;
    to_half_all<<<(n4_all + 255) / 256, 256>>>(x, Wqkv, Wproj, xh, wq, wp);

    // 1) QKV projection (fp16 in, fp16 out for attention)
    gemm_mma<1><<<dim3(24, 128), 256, GEMM_SMEM>>>(xh, wq, bqkv, (const float*)0,
                                                   qkv, ML_, 3 * D_, D_);
    // 2) windowed attention (fp16 tensor cores)
    attn_mma<<<dim3(64, 16, 4), 128, ATTN_SMEM>>>(qkv, attn);
    // 3) output projection + bias + residual (fp32 out)
    gemm_mma<0><<<dim3(8, 128), 256, GEMM_SMEM>>>(attn, wp, bproj, x,
                                                  y, ML_, D_, D_);
    // 4) layernorm (2 rows per block)
    ln_kernel<<<ML_/2, 256>>>(y, gamma, beta, out);
}

// round 12
// speedup vs baseline: 3.1569x; 1.1090x over previous
#include <cuda_runtime.h>
#include <cuda_fp16.h>
#include <cstdint>

#define B_ 4
#define L_ 4096
#define D_ 1024
#define H_ 16
#define W_ 64
#define HD_ 64
#define ML_ (B_*L_)      // 16384 rows
#define EPS_ 1e-5f

// Scratch (allocation-free rule: __device__ globals)
__device__ __half g_qkvh[(size_t)ML_ * 3 * D_]; // [B*L, 3*D] fp16
__device__ __half g_attnh[(size_t)ML_ * D_];    // [B*L, D]   fp16
__device__ float  g_y  [(size_t)ML_ * D_];      // pre-LN residual sum (fp32)
__device__ __half g_xh [(size_t)ML_ * D_];      // x in fp16
__device__ __half g_wqh[(size_t)3 * D_ * D_];   // Wqkv fp16
__device__ __half g_wph[(size_t)D_ * D_];       // Wproj fp16

// ---------------------------------------------------------------------------
__device__ __forceinline__ uint32_t smem_u32(const void* p) {
    uint32_t a;
    asm("{ .reg .u64 t; cvta.to.shared.u64 t, %1; cvt.u32.u64 %0, t; }"
        : "=r"(a) : "l"(p));
    return a;
}
__device__ __forceinline__ void cp16(uint32_t dst, const void* src) {
    asm volatile("cp.async.cg.shared.global [%0], [%1], 16;"
                 :: "r"(dst), "l"(src) : "memory");
}
__device__ __forceinline__ void mma_16x8x16_f16(float* c, const uint32_t* a,
                                                const uint32_t* b) {
    asm volatile(
        "mma.sync.aligned.m16n8k16.row.col.f32.f16.f16.f32 "
        "{%0,%1,%2,%3}, {%4,%5,%6,%7}, {%8,%9}, {%0,%1,%2,%3};"
        : "+f"(c[0]), "+f"(c[1]), "+f"(c[2]), "+f"(c[3])
        : "r"(a[0]), "r"(a[1]), "r"(a[2]), "r"(a[3]), "r"(b[0]), "r"(b[1]));
}
__device__ __forceinline__ void ldsm4(uint32_t* r, uint32_t addr) {
    asm volatile("ldmatrix.sync.aligned.m8n8.x4.shared.b16 {%0,%1,%2,%3}, [%4];"
                 : "=r"(r[0]), "=r"(r[1]), "=r"(r[2]), "=r"(r[3]) : "r"(addr));
}
__device__ __forceinline__ void ldsm4t(uint32_t* r, uint32_t addr) {
    asm volatile("ldmatrix.sync.aligned.m8n8.x4.trans.shared.b16 {%0,%1,%2,%3}, [%4];"
                 : "=r"(r[0]), "=r"(r[1]), "=r"(r[2]), "=r"(r[3]) : "r"(addr));
}

// ---------------------------------------------------------------------------
// Fused fp16 conversion prepass: one launch covers xh, wqh, wph.
// ---------------------------------------------------------------------------
#define N4_X  (ML_*D_/4)
#define N4_WQ (3*D_*D_/4)
#define N4_WP (D_*D_/4)

__global__ void to_half_all(const float* __restrict__ x,
                            const float* __restrict__ Wqkv,
                            const float* __restrict__ Wproj,
                            __half* __restrict__ xh,
                            __half* __restrict__ wq,
                            __half* __restrict__ wp)
{
    int i = blockIdx.x * blockDim.x + threadIdx.x;
    const float4* src;
    __half* dst;
    int j;
    if (i < N4_X)                      { src = (const float4*)x;     dst = xh; j = i; }
    else if (i < N4_X + N4_WQ)         { src = (const float4*)Wqkv;  dst = wq; j = i - N4_X; }
    else if (i < N4_X + N4_WQ + N4_WP) { src = (const float4*)Wproj; dst = wp; j = i - N4_X - N4_WQ; }
    else return;
    float4 v = src[j];
    __half2 h0 = __floats2half2_rn(v.x, v.y);
    __half2 h1 = __floats2half2_rn(v.z, v.w);
    ((uint2*)dst)[j] = make_uint2(*(uint32_t*)&h0, *(uint32_t*)&h1);
}

// ---------------------------------------------------------------------------
// fp16 tensor-core GEMM: C = A @ Bw^T + bias (+R / half-out variants)
// CTA 128x128, K-tile 64 (fp16), 3-stage cp.async, 2 CTAs/SM,
// A-fragment double-buffer. K templated -> fully unrolled mainloop,
// shift-based global addressing, constant-folded ring indices.
// ---------------------------------------------------------------------------
#define TS 72                        // halves per smem row (144 B)
#define BUFH (128*TS*2)              // halves per stage (A then B)
#define GEMM_SMEM (3*BUFH*2)         // 110592 B

template<int OUTHALF, int Kc>
__global__ void __launch_bounds__(256, 2) gemm_mma(
    const __half* __restrict__ A, const __half* __restrict__ Bw,
    const float* __restrict__ bias, const float* __restrict__ R,
    void* __restrict__ Cv, int M, int N)
{
    extern __shared__ __half sm[];
    const uint32_t sbase = smem_u32(sm);
    const int tid  = threadIdx.x;
    const int wid  = tid >> 5, lane = tid & 31;
    const int g    = lane >> 2, tg = lane & 3;
    const int wm   = (wid >> 2) << 6;
    const int wn   = (wid & 3) << 5;
    const int bm   = blockIdx.y << 7, bn = blockIdx.x << 7;
    const int r0   = tid >> 3, c0h = (tid & 7) << 3;
    constexpr int ntk = Kc >> 6;                 // K-tiles of 64

    // ldmatrix per-lane byte offsets
    const int lrA = lane & 15;
    const uint32_t aoff = (uint32_t)(((wm + lrA) * TS) << 1)
                        + (uint32_t)(((lane >> 4) & 1) << 4);
    const int lrB = ((lane >> 4) << 3) + (lane & 7);
    const uint32_t boffb = (uint32_t)(((wn + lrB) * TS) << 1)
                         + (uint32_t)(((lane >> 3) & 1) << 4);

    float acc[4][4][4];
#pragma unroll
    for (int mi = 0; mi < 4; mi++)
#pragma unroll
        for (int ni = 0; ni < 4; ni++)
#pragma unroll
            for (int i = 0; i < 4; i++) acc[mi][ni][i] = 0.f;

    auto cp_tile = [&](int kt, int buf) {
        const int kc = kt << 6;
        const uint32_t da = sbase + (uint32_t)((buf * BUFH + r0 * TS + c0h) << 1);
        const uint32_t db = da + (uint32_t)((128 * TS) << 1);
#pragma unroll
        for (int i = 0; i < 4; i++) {
            cp16(da + (uint32_t)(((i << 5) * TS) << 1),
                 A  + (size_t)(bm + r0 + (i << 5)) * Kc + kc + c0h);
            cp16(db + (uint32_t)(((i << 5) * TS) << 1),
                 Bw + (size_t)(bn + r0 + (i << 5)) * Kc + kc + c0h);
        }
        asm volatile("cp.async.commit_group;" ::: "memory");
    };

    cp_tile(0, 0);
    if (ntk > 1) cp_tile(1, 1);

#pragma unroll
    for (int kt = 0; kt < ntk; kt++) {
        const int buf = kt % 3;
        if (kt < ntk - 1)
            asm volatile("cp.async.wait_group 1;" ::: "memory");
        else
            asm volatile("cp.async.wait_group 0;" ::: "memory");
        __syncthreads();

        const uint32_t Ab = sbase + (uint32_t)((buf * BUFH) << 1);
        const uint32_t Bb = Ab + (uint32_t)((128 * TS) << 1);

        // A-fragment software pipeline over 4 k16-steps
        uint32_t afb[2][4][4];
#pragma unroll
        for (int mi = 0; mi < 4; mi++)
            ldsm4(afb[0][mi], Ab + aoff + (uint32_t)(mi * ((TS << 4) << 1)));

#pragma unroll
        for (int ks = 0; ks < 4; ks++) {
            const uint32_t kb = (uint32_t)(ks << 5);   // 16 halves = 32 B
            uint32_t bf[4][2];
#pragma unroll
            for (int p = 0; p < 2; p++) {
                uint32_t t4[4];
                ldsm4(t4, Bb + boffb + (uint32_t)(p * ((TS << 4) << 1)) + kb);
                bf[2*p][0]   = t4[0]; bf[2*p][1]   = t4[1];
                bf[2*p+1][0] = t4[2]; bf[2*p+1][1] = t4[3];
            }
            if (ks < 3) {
                const uint32_t kb2 = (uint32_t)((ks + 1) << 5);
#pragma unroll
                for (int mi = 0; mi < 4; mi++)
                    ldsm4(afb[(ks + 1) & 1][mi],
                          Ab + aoff + (uint32_t)(mi * ((TS << 4) << 1)) + kb2);
            }
#pragma unroll
            for (int ni = 0; ni < 4; ni++)
#pragma unroll
                for (int mi = 0; mi < 4; mi++)
                    mma_16x8x16_f16(acc[mi][ni], afb[ks & 1][mi], bf[ni]);

            // issue next-stage cp.async after 2 MMA batches queued
            if (ks == 1 && kt + 2 < ntk)
                cp_tile(kt + 2, (kt + 2) % 3);
        }
    }

#pragma unroll
    for (int mi = 0; mi < 4; mi++) {
#pragma unroll
        for (int ni = 0; ni < 4; ni++) {
            const int row = bm + wm + (mi << 4) + g;
            const int col = bn + wn + (ni << 3) + (tg << 1);
            float2 bb = *(const float2*)(bias + col);
            float2 v0 = make_float2(acc[mi][ni][0] + bb.x, acc[mi][ni][1] + bb.y);
            float2 v1 = make_float2(acc[mi][ni][2] + bb.x, acc[mi][ni][3] + bb.y);
            if (OUTHALF) {
                __half* Ch = (__half*)Cv;
                *(__half2*)(Ch + (size_t)row * N + col)       = __floats2half2_rn(v0.x, v0.y);
                *(__half2*)(Ch + (size_t)(row + 8) * N + col) = __floats2half2_rn(v1.x, v1.y);
            } else {
                float* Cf = (float*)Cv;
                float2 ra = *(const float2*)(R + (size_t)row * N + col);
                float2 rb = *(const float2*)(R + (size_t)(row + 8) * N + col);
                v0.x += ra.x; v0.y += ra.y; v1.x += rb.x; v1.y += rb.y;
                *(float2*)(Cf + (size_t)row * N + col)       = v0;
                *(float2*)(Cf + (size_t)(row + 8) * N + col) = v1;
            }
        }
    }
}

// ---------------------------------------------------------------------------
// fp16 windowed attention. 1 block = 1 (window, head, batch); 4 warps.
// S=QK^T and O=PV on m16n8k16; V via ldmatrix.trans.
// ---------------------------------------------------------------------------
#define ATTN_SMEM (3*64*TS*2)

__global__ void __launch_bounds__(128) attn_mma(const __half* __restrict__ qkv,
                                                __half* __restrict__ out)
{
    extern __shared__ __half smh[];
    __half* Qs = smh;                // 64 x TS (rows reused for P per-warp)
    __half* Ks = smh +     64 * TS;
    __half* Vs = smh + 2 * 64 * TS;
    const int tid  = threadIdx.x;
    const int wid  = tid >> 5, lane = tid & 31;
    const int g    = lane >> 2, tg = lane & 3;
    const int m0   = wid << 4;
    const size_t base = ((size_t)(blockIdx.z * L_ + blockIdx.x * W_)) * (3 * D_)
                        + blockIdx.y * HD_;

    const uint32_t Qb = smem_u32(Qs);
    const uint32_t Kb = smem_u32(Ks);
    const uint32_t Vb = smem_u32(Vs);

    // ldmatrix per-lane offsets
    const int lrA = lane & 15;
    const uint32_t qoff = (uint32_t)(((m0 + lrA) * TS) << 1)
                        + (uint32_t)(((lane >> 4) & 1) << 4);
    const int lrB = ((lane >> 4) << 3) + (lane & 7);
    const uint32_t koffb = (uint32_t)((lrB * TS) << 1)
                         + (uint32_t)(((lane >> 3) & 1) << 4);
    const uint32_t voffb = (uint32_t)(((((lane >> 3) & 1) * 8 + (lane & 7)) * TS) << 1)
                         + (uint32_t)(((lane >> 4) & 1) << 4);

    // load Q,K,V tiles (64 x 64 halves each), 16B chunks
    for (int i = tid; i < 64 * 8; i += 128) {
        const int r = i >> 3, c = (i & 7) << 3;
        const __half* p = qkv + base + (size_t)r * (3 * D_) + c;
        *(uint4*)(Qs + r * TS + c) = *(const uint4*)(p);
        *(uint4*)(Ks + r * TS + c) = *(const uint4*)(p + D_);
        *(uint4*)(Vs + r * TS + c) = *(const uint4*)(p + 2 * D_);
    }
    __syncthreads();

    // S = Q K^T  (contraction over hd=64: 4 k16-steps)
    float s[8][4];
#pragma unroll
    for (int t = 0; t < 8; t++)
#pragma unroll
        for (int i = 0; i < 4; i++) s[t][i] = 0.f;

#pragma unroll
    for (int ks = 0; ks < 4; ks++) {
        const uint32_t kb = (uint32_t)(ks << 5);
        uint32_t a[4], bfr[8][2];
        ldsm4(a, Qb + qoff + kb);
#pragma unroll
        for (int p = 0; p < 4; p++) {
            uint32_t t4[4];
            ldsm4(t4, Kb + koffb + (uint32_t)(p * ((TS << 4) << 1)) + kb);
            bfr[2*p][0]   = t4[0]; bfr[2*p][1]   = t4[1];
            bfr[2*p+1][0] = t4[2]; bfr[2*p+1][1] = t4[3];
        }
#pragma unroll
        for (int t = 0; t < 8; t++)
            mma_16x8x16_f16(s[t], a, bfr[t]);
    }

    // softmax over 64 cols; rows g (c0,c1) and g+8 (c2,c3)
    float mxl = -3.0e38f, mxh = -3.0e38f;
#pragma unroll
    for (int t = 0; t < 8; t++) {
#pragma unroll
        for (int i = 0; i < 4; i++) s[t][i] *= 0.125f;
        mxl = fmaxf(mxl, fmaxf(s[t][0], s[t][1]));
        mxh = fmaxf(mxh, fmaxf(s[t][2], s[t][3]));
    }
    mxl = fmaxf(mxl, __shfl_xor_sync(0xffffffffu, mxl, 1));
    mxl = fmaxf(mxl, __shfl_xor_sync(0xffffffffu, mxl, 2));
    mxh = fmaxf(mxh, __shfl_xor_sync(0xffffffffu, mxh, 1));
    mxh = fmaxf(mxh, __shfl_xor_sync(0xffffffffu, mxh, 2));

    float sl = 0.f, sh = 0.f;
#pragma unroll
    for (int t = 0; t < 8; t++) {
        s[t][0] = __expf(s[t][0] - mxl); sl += s[t][0];
        s[t][1] = __expf(s[t][1] - mxl); sl += s[t][1];
        s[t][2] = __expf(s[t][2] - mxh); sh += s[t][2];
        s[t][3] = __expf(s[t][3] - mxh); sh += s[t][3];
    }
    sl += __shfl_xor_sync(0xffffffffu, sl, 1);
    sl += __shfl_xor_sync(0xffffffffu, sl, 2);
    sh += __shfl_xor_sync(0xffffffffu, sh, 1);
    sh += __shfl_xor_sync(0xffffffffu, sh, 2);
    const float il = 1.0f / sl, ih = 1.0f / sh;

    // write P (fp16) into this warp's private Q rows
#pragma unroll
    for (int t = 0; t < 8; t++) {
        const int cc = (t << 3) + (tg << 1);
        *(__half2*)(Qs + (m0 + g) * TS + cc) =
            __floats2half2_rn(s[t][0] * il, s[t][1] * il);
        *(__half2*)(Qs + (m0 + g + 8) * TS + cc) =
            __floats2half2_rn(s[t][2] * ih, s[t][3] * ih);
    }
    __syncwarp();

    // O = P V  (contraction over 64 keys: 4 k16-steps, V via trans-ldmatrix)
    float o[8][4];
#pragma unroll
    for (int t = 0; t < 8; t++)
#pragma unroll
        for (int i = 0; i < 4; i++) o[t][i] = 0.f;

#pragma unroll
    for (int ks = 0; ks < 4; ks++) {
        uint32_t a[4];
        ldsm4(a, Qb + qoff + (uint32_t)(ks << 5));
        const uint32_t vkb = (uint32_t)(ks * ((TS << 4) << 1));  // 16 key-rows
#pragma unroll
        for (int p = 0; p < 4; p++) {
            uint32_t t4[4];
            ldsm4t(t4, Vb + voffb + vkb + (uint32_t)(p << 5));   // p*16 hd-cols
            uint32_t b0[2] = { t4[0], t4[1] };
            uint32_t b1[2] = { t4[2], t4[3] };
            mma_16x8x16_f16(o[2*p],   a, b0);
            mma_16x8x16_f16(o[2*p+1], a, b1);
        }
    }

    // store O (fp16: feeds the proj GEMM)
    const size_t row = (size_t)(blockIdx.z * L_ + blockIdx.x * W_ + m0 + g);
    const int colb = blockIdx.y * HD_;
#pragma unroll
    for (int t = 0; t < 8; t++) {
        const int cc = colb + (t << 3) + (tg << 1);
        *(__half2*)(out + row * D_ + cc)       = __floats2half2_rn(o[t][0], o[t][1]);
        *(__half2*)(out + (row + 8) * D_ + cc) = __floats2half2_rn(o[t][2], o[t][3]);
    }
}

// ---------------------------------------------------------------------------
// LayerNorm: one block per 2 rows of 1024.
// ---------------------------------------------------------------------------
__global__ void __launch_bounds__(256) ln_kernel(const float* __restrict__ y,
                                                 const float* __restrict__ gamma,
                                                 const float* __restrict__ beta,
                                                 float* __restrict__ out)
{
    __shared__ float red[8];
    const int tid = threadIdx.x;
    float4 gm = *(const float4*)(gamma + (tid << 2));
    float4 be = *(const float4*)(beta  + (tid << 2));

#pragma unroll
    for (int rr = 0; rr < 2; rr++) {
        const int row = (blockIdx.x << 1) + rr;
        const float* yr = y + (size_t)row * D_;
        float4 v = *(const float4*)(yr + (tid << 2));

        float sAcc = v.x + v.y + v.z + v.w;
#pragma unroll
        for (int o = 16; o > 0; o >>= 1) sAcc += __shfl_xor_sync(0xffffffffu, sAcc, o);
        if ((tid & 31) == 0) red[tid >> 5] = sAcc;
        __syncthreads();
        float tot = 0.f;
#pragma unroll
        for (int i = 0; i < 8; i++) tot += red[i];
        const float mean = tot * (1.0f / 1024.0f);

        const float dx = v.x - mean, dy = v.y - mean, dz = v.z - mean, dw = v.w - mean;
        float s2 = dx * dx + dy * dy + dz * dz + dw * dw;
#pragma unroll
        for (int o = 16; o > 0; o >>= 1) s2 += __shfl_xor_sync(0xffffffffu, s2, o);
        __syncthreads();
        if ((tid & 31) == 0) red[tid >> 5] = s2;
        __syncthreads();
        float tot2 = 0.f;
#pragma unroll
        for (int i = 0; i < 8; i++) tot2 += red[i];
        const float rstd = rsqrtf(tot2 * (1.0f / 1024.0f) + EPS_);

        float4 o4 = make_float4(dx * rstd * gm.x + be.x,
                                dy * rstd * gm.y + be.y,
                                dz * rstd * gm.z + be.z,
                                dw * rstd * gm.w + be.w);
        *(float4*)(out + (size_t)row * D_ + (tid << 2)) = o4;
        if (rr == 0) __syncthreads();
    }
}

// ---------------------------------------------------------------------------
extern "C" void kernel_launch(void* const* d_in, const int* in_sizes, int n_in,
                              void* d_out, int out_size)
{
    const float* x     = (const float*)d_in[0];
    const float* Wqkv  = (const float*)d_in[1];
    const float* bqkv  = (const float*)d_in[2];
    const float* Wproj = (const float*)d_in[3];
    const float* bproj = (const float*)d_in[4];
    const float* gamma = (const float*)d_in[5];
    const float* beta  = (const float*)d_in[6];
    float* out = (float*)d_out;

    __half *qkv, *attn, *xh, *wq, *wp;
    float *y;
    cudaGetSymbolAddress((void**)&qkv,  g_qkvh);
    cudaGetSymbolAddress((void**)&attn, g_attnh);
    cudaGetSymbolAddress((void**)&y,    g_y);
    cudaGetSymbolAddress((void**)&xh,   g_xh);
    cudaGetSymbolAddress((void**)&wq,   g_wqh);
    cudaGetSymbolAddress((void**)&wp,   g_wph);

    cudaFuncSetAttribute((const void*)gemm_mma<1,1024>,
                         cudaFuncAttributeMaxDynamicSharedMemorySize, GEMM_SMEM);
    cudaFuncSetAttribute((const void*)gemm_mma<0,1024>,
                         cudaFuncAttributeMaxDynamicSharedMemorySize, GEMM_SMEM);
    cudaFuncSetAttribute(attn_mma, cudaFuncAttributeMaxDynamicSharedMemorySize, ATTN_SMEM);

    // 0) convert all GEMM operands to fp16 in one launch
    const int n4_all = N4_X + N4_WQ + N4_WP;
    to_half_all<<<(n4_all + 255) / 256, 256>>>(x, Wqkv, Wproj, xh, wq, wp);

    // 1) QKV projection (fp16 in, fp16 out for attention)
    gemm_mma<1,1024><<<dim3(24, 128), 256, GEMM_SMEM>>>(xh, wq, bqkv,
                                                        (const float*)0, qkv,
                                                        ML_, 3 * D_);
    // 2) windowed attention (fp16 tensor cores)
    attn_mma<<<dim3(64, 16, 4), 128, ATTN_SMEM>>>(qkv, attn);
    // 3) output projection + bias + residual (fp32 out)
    gemm_mma<0,1024><<<dim3(8, 128), 256, GEMM_SMEM>>>(attn, wp, bproj, x,
                                                       y, ML_, D_);
    // 4) layernorm (2 rows per block)
    ln_kernel<<<ML_/2, 256>>>(y, gamma, beta, out);
}

// round 14
// speedup vs baseline: 3.2826x; 1.0398x over previous
#include <cuda_runtime.h>
#include <cuda_fp16.h>
#include <cstdint>

#define B_ 4
#define L_ 4096
#define D_ 1024
#define H_ 16
#define W_ 64
#define HD_ 64
#define ML_ (B_*L_)      // 16384 rows
#define EPS_ 1e-5f

// Scratch (allocation-free rule: __device__ globals)
__device__ __half g_qkvh[(size_t)ML_ * 3 * D_]; // [B*L, 3*D] fp16
__device__ __half g_attnh[(size_t)ML_ * D_];    // [B*L, D]   fp16
__device__ float  g_y  [(size_t)ML_ * D_];      // pre-LN residual sum (fp32)
__device__ __half g_xh [(size_t)ML_ * D_];      // x in fp16
__device__ __half g_wqh[(size_t)3 * D_ * D_];   // Wqkv fp16
__device__ __half g_wph[(size_t)D_ * D_];       // Wproj fp16

// ---------------------------------------------------------------------------
__device__ __forceinline__ uint32_t smem_u32(const void* p) {
    uint32_t a;
    asm("{ .reg .u64 t; cvta.to.shared.u64 t, %1; cvt.u32.u64 %0, t; }"
        : "=r"(a) : "l"(p));
    return a;
}
__device__ __forceinline__ void cp16(uint32_t dst, const void* src) {
    asm volatile("cp.async.cg.shared.global [%0], [%1], 16;"
                 :: "r"(dst), "l"(src) : "memory");
}
__device__ __forceinline__ void mma_16x8x16_f16(float* c, const uint32_t* a,
                                                const uint32_t* b) {
    asm volatile(
        "mma.sync.aligned.m16n8k16.row.col.f32.f16.f16.f32 "
        "{%0,%1,%2,%3}, {%4,%5,%6,%7}, {%8,%9}, {%0,%1,%2,%3};"
        : "+f"(c[0]), "+f"(c[1]), "+f"(c[2]), "+f"(c[3])
        : "r"(a[0]), "r"(a[1]), "r"(a[2]), "r"(a[3]), "r"(b[0]), "r"(b[1]));
}
__device__ __forceinline__ void ldsm4(uint32_t* r, uint32_t addr) {
    asm volatile("ldmatrix.sync.aligned.m8n8.x4.shared.b16 {%0,%1,%2,%3}, [%4];"
                 : "=r"(r[0]), "=r"(r[1]), "=r"(r[2]), "=r"(r[3]) : "r"(addr));
}
__device__ __forceinline__ void ldsm4t(uint32_t* r, uint32_t addr) {
    asm volatile("ldmatrix.sync.aligned.m8n8.x4.trans.shared.b16 {%0,%1,%2,%3}, [%4];"
                 : "=r"(r[0]), "=r"(r[1]), "=r"(r[2]), "=r"(r[3]) : "r"(addr));
}

// ---------------------------------------------------------------------------
// Fused fp16 conversion prepass: one launch covers xh, wqh, wph.
// ---------------------------------------------------------------------------
#define N4_X  (ML_*D_/4)
#define N4_WQ (3*D_*D_/4)
#define N4_WP (D_*D_/4)

__global__ void to_half_all(const float* __restrict__ x,
                            const float* __restrict__ Wqkv,
                            const float* __restrict__ Wproj,
                            __half* __restrict__ xh,
                            __half* __restrict__ wq,
                            __half* __restrict__ wp)
{
    int i = blockIdx.x * blockDim.x + threadIdx.x;
    const float4* src;
    __half* dst;
    int j;
    if (i < N4_X)                      { src = (const float4*)x;     dst = xh; j = i; }
    else if (i < N4_X + N4_WQ)         { src = (const float4*)Wqkv;  dst = wq; j = i - N4_X; }
    else if (i < N4_X + N4_WQ + N4_WP) { src = (const float4*)Wproj; dst = wp; j = i - N4_X - N4_WQ; }
    else return;
    float4 v = src[j];
    __half2 h0 = __floats2half2_rn(v.x, v.y);
    __half2 h1 = __floats2half2_rn(v.z, v.w);
    ((uint2*)dst)[j] = make_uint2(*(uint32_t*)&h0, *(uint32_t*)&h1);
}

// ---------------------------------------------------------------------------
// fp16 tensor-core GEMM: C = A @ Bw^T + bias (+R / half-out variants)
// CTA 128x128, K-tile 64 (fp16), 3-stage cp.async, 2 CTAs/SM,
// A-fragment double-buffer, unrolled K. OUTHALF epilogue stages the C tile
// through smem for fully-coalesced 16B stores.
// ---------------------------------------------------------------------------
#define TS 72                        // halves per smem row (144 B)
#define BUFH (128*TS*2)              // halves per stage (A then B)
#define GEMM_SMEM (3*BUFH*2)         // 110592 B
#define CSTRIDE 136                  // epilogue staging stride (halves)

template<int OUTHALF, int Kc>
__global__ void __launch_bounds__(256, 2) gemm_mma(
    const __half* __restrict__ A, const __half* __restrict__ Bw,
    const float* __restrict__ bias, const float* __restrict__ R,
    void* __restrict__ Cv, int M, int N)
{
    extern __shared__ __half sm[];
    const uint32_t sbase = smem_u32(sm);
    const int tid  = threadIdx.x;
    const int wid  = tid >> 5, lane = tid & 31;
    const int g    = lane >> 2, tg = lane & 3;
    const int wm   = (wid >> 2) << 6;
    const int wn   = (wid & 3) << 5;
    const int bm   = blockIdx.y << 7, bn = blockIdx.x << 7;
    const int r0   = tid >> 3, c0h = (tid & 7) << 3;
    constexpr int ntk = Kc >> 6;                 // K-tiles of 64

    // ldmatrix per-lane byte offsets
    const int lrA = lane & 15;
    const uint32_t aoff = (uint32_t)(((wm + lrA) * TS) << 1)
                        + (uint32_t)(((lane >> 4) & 1) << 4);
    const int lrB = ((lane >> 4) << 3) + (lane & 7);
    const uint32_t boffb = (uint32_t)(((wn + lrB) * TS) << 1)
                         + (uint32_t)(((lane >> 3) & 1) << 4);

    float acc[4][4][4];
#pragma unroll
    for (int mi = 0; mi < 4; mi++)
#pragma unroll
        for (int ni = 0; ni < 4; ni++)
#pragma unroll
            for (int i = 0; i < 4; i++) acc[mi][ni][i] = 0.f;

    auto cp_tile = [&](int kt, int buf) {
        const int kc = kt << 6;
        const uint32_t da = sbase + (uint32_t)((buf * BUFH + r0 * TS + c0h) << 1);
        const uint32_t db = da + (uint32_t)((128 * TS) << 1);
#pragma unroll
        for (int i = 0; i < 4; i++) {
            cp16(da + (uint32_t)(((i << 5) * TS) << 1),
                 A  + (size_t)(bm + r0 + (i << 5)) * Kc + kc + c0h);
            cp16(db + (uint32_t)(((i << 5) * TS) << 1),
                 Bw + (size_t)(bn + r0 + (i << 5)) * Kc + kc + c0h);
        }
        asm volatile("cp.async.commit_group;" ::: "memory");
    };

    cp_tile(0, 0);
    if (ntk > 1) cp_tile(1, 1);

#pragma unroll
    for (int kt = 0; kt < ntk; kt++) {
        const int buf = kt % 3;
        if (kt < ntk - 1)
            asm volatile("cp.async.wait_group 1;" ::: "memory");
        else
            asm volatile("cp.async.wait_group 0;" ::: "memory");
        __syncthreads();

        const uint32_t Ab = sbase + (uint32_t)((buf * BUFH) << 1);
        const uint32_t Bb = Ab + (uint32_t)((128 * TS) << 1);

        // A-fragment software pipeline over 4 k16-steps
        uint32_t afb[2][4][4];
#pragma unroll
        for (int mi = 0; mi < 4; mi++)
            ldsm4(afb[0][mi], Ab + aoff + (uint32_t)(mi * ((TS << 4) << 1)));

#pragma unroll
        for (int ks = 0; ks < 4; ks++) {
            const uint32_t kb = (uint32_t)(ks << 5);   // 16 halves = 32 B
            uint32_t bf[4][2];
#pragma unroll
            for (int p = 0; p < 2; p++) {
                uint32_t t4[4];
                ldsm4(t4, Bb + boffb + (uint32_t)(p * ((TS << 4) << 1)) + kb);
                bf[2*p][0]   = t4[0]; bf[2*p][1]   = t4[1];
                bf[2*p+1][0] = t4[2]; bf[2*p+1][1] = t4[3];
            }
            if (ks < 3) {
                const uint32_t kb2 = (uint32_t)((ks + 1) << 5);
#pragma unroll
                for (int mi = 0; mi < 4; mi++)
                    ldsm4(afb[(ks + 1) & 1][mi],
                          Ab + aoff + (uint32_t)(mi * ((TS << 4) << 1)) + kb2);
            }
#pragma unroll
            for (int ni = 0; ni < 4; ni++)
#pragma unroll
                for (int mi = 0; mi < 4; mi++)
                    mma_16x8x16_f16(acc[mi][ni], afb[ks & 1][mi], bf[ni]);

            // issue next-stage cp.async after 2 MMA batches queued
            if (ks == 1 && kt + 2 < ntk)
                cp_tile(kt + 2, (kt + 2) % 3);
        }
    }

    if (OUTHALF) {
        // stage C tile (post-bias, fp16) in smem, then coalesced 16B stores
        __syncthreads();    // all warps done reading stage buffers
#pragma unroll
        for (int mi = 0; mi < 4; mi++) {
#pragma unroll
            for (int ni = 0; ni < 4; ni++) {
                const int rl = wm + (mi << 4) + g;
                const int cl = wn + (ni << 3) + (tg << 1);
                float2 bb = *(const float2*)(bias + bn + cl);
                *(__half2*)(sm + rl * CSTRIDE + cl) =
                    __floats2half2_rn(acc[mi][ni][0] + bb.x, acc[mi][ni][1] + bb.y);
                *(__half2*)(sm + (rl + 8) * CSTRIDE + cl) =
                    __floats2half2_rn(acc[mi][ni][2] + bb.x, acc[mi][ni][3] + bb.y);
            }
        }
        __syncthreads();
        __half* Ch = (__half*)Cv;
        const int rw = tid >> 4;            // 16 rows per pass
        const int ck = (tid & 15) << 3;     // 8 halves = 16B per thread
#pragma unroll
        for (int p = 0; p < 8; p++) {
            const int r = (p << 4) + rw;
            uint4 v = *(const uint4*)(sm + r * CSTRIDE + ck);
            *(uint4*)(Ch + (size_t)(bm + r) * N + bn + ck) = v;
        }
    } else {
        // fp32 out (+residual): float2x4-lane stores are already sector-perfect
#pragma unroll
        for (int mi = 0; mi < 4; mi++) {
#pragma unroll
            for (int ni = 0; ni < 4; ni++) {
                const int row = bm + wm + (mi << 4) + g;
                const int col = bn + wn + (ni << 3) + (tg << 1);
                float2 bb = *(const float2*)(bias + col);
                float2 v0 = make_float2(acc[mi][ni][0] + bb.x, acc[mi][ni][1] + bb.y);
                float2 v1 = make_float2(acc[mi][ni][2] + bb.x, acc[mi][ni][3] + bb.y);
                float* Cf = (float*)Cv;
                float2 ra = *(const float2*)(R + (size_t)row * N + col);
                float2 rb = *(const float2*)(R + (size_t)(row + 8) * N + col);
                v0.x += ra.x; v0.y += ra.y; v1.x += rb.x; v1.y += rb.y;
                *(float2*)(Cf + (size_t)row * N + col)       = v0;
                *(float2*)(Cf + (size_t)(row + 8) * N + col) = v1;
            }
        }
    }
}

// ---------------------------------------------------------------------------
// fp16 windowed attention. 1 block = 1 (window, head, batch); 4 warps.
// S=QK^T and O=PV on m16n8k16; V via ldmatrix.trans. Output staged through
// smem (Ks region, free after S-phase) for coalesced 16B stores.
// ---------------------------------------------------------------------------
#define ATTN_SMEM (3*64*TS*2)

__global__ void __launch_bounds__(128) attn_mma(const __half* __restrict__ qkv,
                                                __half* __restrict__ out)
{
    extern __shared__ __half smh[];
    __half* Qs = smh;                // 64 x TS (rows reused for P per-warp)
    __half* Ks = smh +     64 * TS;  // reused as O staging after S-phase
    __half* Vs = smh + 2 * 64 * TS;
    const int tid  = threadIdx.x;
    const int wid  = tid >> 5, lane = tid & 31;
    const int g    = lane >> 2, tg = lane & 3;
    const int m0   = wid << 4;
    const size_t base = ((size_t)(blockIdx.z * L_ + blockIdx.x * W_)) * (3 * D_)
                        + blockIdx.y * HD_;

    const uint32_t Qb = smem_u32(Qs);
    const uint32_t Kb = smem_u32(Ks);
    const uint32_t Vb = smem_u32(Vs);

    // ldmatrix per-lane offsets
    const int lrA = lane & 15;
    const uint32_t qoff = (uint32_t)(((m0 + lrA) * TS) << 1)
                        + (uint32_t)(((lane >> 4) & 1) << 4);
    const int lrB = ((lane >> 4) << 3) + (lane & 7);
    const uint32_t koffb = (uint32_t)((lrB * TS) << 1)
                         + (uint32_t)(((lane >> 3) & 1) << 4);
    const uint32_t voffb = (uint32_t)(((((lane >> 3) & 1) * 8 + (lane & 7)) * TS) << 1)
                         + (uint32_t)(((lane >> 4) & 1) << 4);

    // load Q,K,V tiles (64 x 64 halves each), 16B chunks
    for (int i = tid; i < 64 * 8; i += 128) {
        const int r = i >> 3, c = (i & 7) << 3;
        const __half* p = qkv + base + (size_t)r * (3 * D_) + c;
        *(uint4*)(Qs + r * TS + c) = *(const uint4*)(p);
        *(uint4*)(Ks + r * TS + c) = *(const uint4*)(p + D_);
        *(uint4*)(Vs + r * TS + c) = *(const uint4*)(p + 2 * D_);
    }
    __syncthreads();

    // S = Q K^T  (contraction over hd=64: 4 k16-steps)
    float s[8][4];
#pragma unroll
    for (int t = 0; t < 8; t++)
#pragma unroll
        for (int i = 0; i < 4; i++) s[t][i] = 0.f;

#pragma unroll
    for (int ks = 0; ks < 4; ks++) {
        const uint32_t kb = (uint32_t)(ks << 5);
        uint32_t a[4], bfr[8][2];
        ldsm4(a, Qb + qoff + kb);
#pragma unroll
        for (int p = 0; p < 4; p++) {
            uint32_t t4[4];
            ldsm4(t4, Kb + koffb + (uint32_t)(p * ((TS << 4) << 1)) + kb);
            bfr[2*p][0]   = t4[0]; bfr[2*p][1]   = t4[1];
            bfr[2*p+1][0] = t4[2]; bfr[2*p+1][1] = t4[3];
        }
#pragma unroll
        for (int t = 0; t < 8; t++)
            mma_16x8x16_f16(s[t], a, bfr[t]);
    }

    // softmax over 64 cols; rows g (c0,c1) and g+8 (c2,c3)
    float mxl = -3.0e38f, mxh = -3.0e38f;
#pragma unroll
    for (int t = 0; t < 8; t++) {
#pragma unroll
        for (int i = 0; i < 4; i++) s[t][i] *= 0.125f;
        mxl = fmaxf(mxl, fmaxf(s[t][0], s[t][1]));
        mxh = fmaxf(mxh, fmaxf(s[t][2], s[t][3]));
    }
    mxl = fmaxf(mxl, __shfl_xor_sync(0xffffffffu, mxl, 1));
    mxl = fmaxf(mxl, __shfl_xor_sync(0xffffffffu, mxl, 2));
    mxh = fmaxf(mxh, __shfl_xor_sync(0xffffffffu, mxh, 1));
    mxh = fmaxf(mxh, __shfl_xor_sync(0xffffffffu, mxh, 2));

    float sl = 0.f, sh = 0.f;
#pragma unroll
    for (int t = 0; t < 8; t++) {
        s[t][0] = __expf(s[t][0] - mxl); sl += s[t][0];
        s[t][1] = __expf(s[t][1] - mxl); sl += s[t][1];
        s[t][2] = __expf(s[t][2] - mxh); sh += s[t][2];
        s[t][3] = __expf(s[t][3] - mxh); sh += s[t][3];
    }
    sl += __shfl_xor_sync(0xffffffffu, sl, 1);
    sl += __shfl_xor_sync(0xffffffffu, sl, 2);
    sh += __shfl_xor_sync(0xffffffffu, sh, 1);
    sh += __shfl_xor_sync(0xffffffffu, sh, 2);
    const float il = 1.0f / sl, ih = 1.0f / sh;

    // write P (fp16) into this warp's private Q rows
#pragma unroll
    for (int t = 0; t < 8; t++) {
        const int cc = (t << 3) + (tg << 1);
        *(__half2*)(Qs + (m0 + g) * TS + cc) =
            __floats2half2_rn(s[t][0] * il, s[t][1] * il);
        *(__half2*)(Qs + (m0 + g + 8) * TS + cc) =
            __floats2half2_rn(s[t][2] * ih, s[t][3] * ih);
    }
    __syncwarp();

    // O = P V  (contraction over 64 keys: 4 k16-steps, V via trans-ldmatrix)
    float o[8][4];
#pragma unroll
    for (int t = 0; t < 8; t++)
#pragma unroll
        for (int i = 0; i < 4; i++) o[t][i] = 0.f;

#pragma unroll
    for (int ks = 0; ks < 4; ks++) {
        uint32_t a[4];
        ldsm4(a, Qb + qoff + (uint32_t)(ks << 5));
        const uint32_t vkb = (uint32_t)(ks * ((TS << 4) << 1));  // 16 key-rows
#pragma unroll
        for (int p = 0; p < 4; p++) {
            uint32_t t4[4];
            ldsm4t(t4, Vb + voffb + vkb + (uint32_t)(p << 5));   // p*16 hd-cols
            uint32_t b0[2] = { t4[0], t4[1] };
            uint32_t b1[2] = { t4[2], t4[3] };
            mma_16x8x16_f16(o[2*p],   a, b0);
            mma_16x8x16_f16(o[2*p+1], a, b1);
        }
    }

    // stage O in Ks (all warps past S-phase after this barrier), then
    // cooperative coalesced 16B stores
    __syncthreads();
#pragma unroll
    for (int t = 0; t < 8; t++) {
        const int cc = (t << 3) + (tg << 1);
        *(__half2*)(Ks + (m0 + g) * TS + cc)       = __floats2half2_rn(o[t][0], o[t][1]);
        *(__half2*)(Ks + (m0 + g + 8) * TS + cc)   = __floats2half2_rn(o[t][2], o[t][3]);
    }
    __syncthreads();

    const size_t rowbase = (size_t)(blockIdx.z * L_ + blockIdx.x * W_);
    const int colb = blockIdx.y * HD_;
    const int rw = tid >> 3;            // 16 rows per pass
    const int ck = (tid & 7) << 3;      // 8 halves = 16B
#pragma unroll
    for (int p = 0; p < 4; p++) {
        const int r = (p << 4) + rw;
        uint4 v = *(const uint4*)(Ks + r * TS + ck);
        *(uint4*)(out + (rowbase + r) * D_ + colb + ck) = v;
    }
}

// ---------------------------------------------------------------------------
// LayerNorm: one block per 2 rows of 1024.
// ---------------------------------------------------------------------------
__global__ void __launch_bounds__(256) ln_kernel(const float* __restrict__ y,
                                                 const float* __restrict__ gamma,
                                                 const float* __restrict__ beta,
                                                 float* __restrict__ out)
{
    __shared__ float red[8];
    const int tid = threadIdx.x;
    float4 gm = *(const float4*)(gamma + (tid << 2));
    float4 be = *(const float4*)(beta  + (tid << 2));

#pragma unroll
    for (int rr = 0; rr < 2; rr++) {
        const int row = (blockIdx.x << 1) + rr;
        const float* yr = y + (size_t)row * D_;
        float4 v = *(const float4*)(yr + (tid << 2));

        float sAcc = v.x + v.y + v.z + v.w;
#pragma unroll
        for (int o = 16; o > 0; o >>= 1) sAcc += __shfl_xor_sync(0xffffffffu, sAcc, o);
        if ((tid & 31) == 0) red[tid >> 5] = sAcc;
        __syncthreads();
        float tot = 0.f;
#pragma unroll
        for (int i = 0; i < 8; i++) tot += red[i];
        const float mean = tot * (1.0f / 1024.0f);

        const float dx = v.x - mean, dy = v.y - mean, dz = v.z - mean, dw = v.w - mean;
        float s2 = dx * dx + dy * dy + dz * dz + dw * dw;
#pragma unroll
        for (int o = 16; o > 0; o >>= 1) s2 += __shfl_xor_sync(0xffffffffu, s2, o);
        __syncthreads();
        if ((tid & 31) == 0) red[tid >> 5] = s2;
        __syncthreads();
        float tot2 = 0.f;
#pragma unroll
        for (int i = 0; i < 8; i++) tot2 += red[i];
        const float rstd = rsqrtf(tot2 * (1.0f / 1024.0f) + EPS_);

        float4 o4 = make_float4(dx * rstd * gm.x + be.x,
                                dy * rstd * gm.y + be.y,
                                dz * rstd * gm.z + be.z,
                                dw * rstd * gm.w + be.w);
        *(float4*)(out + (size_t)row * D_ + (tid << 2)) = o4;
        if (rr == 0) __syncthreads();
    }
}

// ---------------------------------------------------------------------------
extern "C" void kernel_launch(void* const* d_in, const int* in_sizes, int n_in,
                              void* d_out, int out_size)
{
    const float* x     = (const float*)d_in[0];
    const float* Wqkv  = (const float*)d_in[1];
    const float* bqkv  = (const float*)d_in[2];
    const float* Wproj = (const float*)d_in[3];
    const float* bproj = (const float*)d_in[4];
    const float* gamma = (const float*)d_in[5];
    const float* beta  = (const float*)d_in[6];
    float* out = (float*)d_out;

    __half *qkv, *attn, *xh, *wq, *wp;
    float *y;
    cudaGetSymbolAddress((void**)&qkv,  g_qkvh);
    cudaGetSymbolAddress((void**)&attn, g_attnh);
    cudaGetSymbolAddress((void**)&y,    g_y);
    cudaGetSymbolAddress((void**)&xh,   g_xh);
    cudaGetSymbolAddress((void**)&wq,   g_wqh);
    cudaGetSymbolAddress((void**)&wp,   g_wph);

    cudaFuncSetAttribute((const void*)gemm_mma<1,1024>,
                         cudaFuncAttributeMaxDynamicSharedMemorySize, GEMM_SMEM);
    cudaFuncSetAttribute((const void*)gemm_mma<0,1024>,
                         cudaFuncAttributeMaxDynamicSharedMemorySize, GEMM_SMEM);
    cudaFuncSetAttribute(attn_mma, cudaFuncAttributeMaxDynamicSharedMemorySize, ATTN_SMEM);

    // 0) convert all GEMM operands to fp16 in one launch
    const int n4_all = N4_X + N4_WQ + N4_WP;
    to_half_all<<<(n4_all + 255) / 256, 256>>>(x, Wqkv, Wproj, xh, wq, wp);

    // 1) QKV projection (fp16 in, fp16 out, coalesced epilogue)
    gemm_mma<1,1024><<<dim3(24, 128), 256, GEMM_SMEM>>>(xh, wq, bqkv,
                                                        (const float*)0, qkv,
                                                        ML_, 3 * D_);
    // 2) windowed attention (fp16 tensor cores, coalesced epilogue)
    attn_mma<<<dim3(64, 16, 4), 128, ATTN_SMEM>>>(qkv, attn);
    // 3) output projection + bias + residual (fp32 out)
    gemm_mma<0,1024><<<dim3(8, 128), 256, GEMM_SMEM>>>(attn, wp, bproj, x,
                                                       y, ML_, D_);
    // 4) layernorm (2 rows per block)
    ln_kernel<<<ML_/2, 256>>>(y, gamma, beta, out);
}

// round 15
// speedup vs baseline: 3.2852x; 1.0008x over previous
#include <cuda_runtime.h>
#include <cuda_fp16.h>
#include <cstdint>

#define B_ 4
#define L_ 4096
#define D_ 1024
#define H_ 16
#define W_ 64
#define HD_ 64
#define ML_ (B_*L_)      // 16384 rows
#define EPS_ 1e-5f

// Scratch (allocation-free rule: __device__ globals)
__device__ __half g_qkvh[(size_t)ML_ * 3 * D_]; // [B*L, 3*D] fp16
__device__ __half g_attnh[(size_t)ML_ * D_];    // [B*L, D]   fp16
__device__ float  g_y  [(size_t)ML_ * D_];      // pre-LN residual sum (fp32)
__device__ __half g_xh [(size_t)ML_ * D_];      // x in fp16
__device__ __half g_wqh[(size_t)3 * D_ * D_];   // Wqkv fp16
__device__ __half g_wph[(size_t)D_ * D_];       // Wproj fp16

// ---------------------------------------------------------------------------
__device__ __forceinline__ uint32_t smem_u32(const void* p) {
    uint32_t a;
    asm("{ .reg .u64 t; cvta.to.shared.u64 t, %1; cvt.u32.u64 %0, t; }"
        : "=r"(a) : "l"(p));
    return a;
}
__device__ __forceinline__ void cp16(uint32_t dst, const void* src) {
    asm volatile("cp.async.cg.shared.global [%0], [%1], 16;"
                 :: "r"(dst), "l"(src) : "memory");
}
// L1-cached variant: used for weight (B) tiles shared by co-resident CTAs
__device__ __forceinline__ void cp16ca(uint32_t dst, const void* src) {
    asm volatile("cp.async.ca.shared.global [%0], [%1], 16;"
                 :: "r"(dst), "l"(src) : "memory");
}
__device__ __forceinline__ void mma_16x8x16_f16(float* c, const uint32_t* a,
                                                const uint32_t* b) {
    asm volatile(
        "mma.sync.aligned.m16n8k16.row.col.f32.f16.f16.f32 "
        "{%0,%1,%2,%3}, {%4,%5,%6,%7}, {%8,%9}, {%0,%1,%2,%3};"
        : "+f"(c[0]), "+f"(c[1]), "+f"(c[2]), "+f"(c[3])
        : "r"(a[0]), "r"(a[1]), "r"(a[2]), "r"(a[3]), "r"(b[0]), "r"(b[1]));
}
__device__ __forceinline__ void ldsm4(uint32_t* r, uint32_t addr) {
    asm volatile("ldmatrix.sync.aligned.m8n8.x4.shared.b16 {%0,%1,%2,%3}, [%4];"
                 : "=r"(r[0]), "=r"(r[1]), "=r"(r[2]), "=r"(r[3]) : "r"(addr));
}
__device__ __forceinline__ void ldsm4t(uint32_t* r, uint32_t addr) {
    asm volatile("ldmatrix.sync.aligned.m8n8.x4.trans.shared.b16 {%0,%1,%2,%3}, [%4];"
                 : "=r"(r[0]), "=r"(r[1]), "=r"(r[2]), "=r"(r[3]) : "r"(addr));
}

// ---------------------------------------------------------------------------
// Fused fp16 conversion prepass: one launch covers xh, wqh, wph.
// ---------------------------------------------------------------------------
#define N4_X  (ML_*D_/4)
#define N4_WQ (3*D_*D_/4)
#define N4_WP (D_*D_/4)

__global__ void to_half_all(const float* __restrict__ x,
                            const float* __restrict__ Wqkv,
                            const float* __restrict__ Wproj,
                            __half* __restrict__ xh,
                            __half* __restrict__ wq,
                            __half* __restrict__ wp)
{
    int i = blockIdx.x * blockDim.x + threadIdx.x;
    const float4* src;
    __half* dst;
    int j;
    if (i < N4_X)                      { src = (const float4*)x;     dst = xh; j = i; }
    else if (i < N4_X + N4_WQ)         { src = (const float4*)Wqkv;  dst = wq; j = i - N4_X; }
    else if (i < N4_X + N4_WQ + N4_WP) { src = (const float4*)Wproj; dst = wp; j = i - N4_X - N4_WQ; }
    else return;
    float4 v = src[j];
    __half2 h0 = __floats2half2_rn(v.x, v.y);
    __half2 h1 = __floats2half2_rn(v.z, v.w);
    ((uint2*)dst)[j] = make_uint2(*(uint32_t*)&h0, *(uint32_t*)&h1);
}

// ---------------------------------------------------------------------------
// fp16 tensor-core GEMM: C = A @ Bw^T + bias (+R / half-out variants)
// CTA 128x128, K-tile 64 (fp16), 3-stage cp.async, 2 CTAs/SM.
// Grid mapping: blockIdx.x = M-tile (fastest), blockIdx.y = N-tile, so
// co-resident CTAs share the same weight (B) tile; B loaded with .ca to
// exploit L1 sharing between the SM's two CTAs.
// ---------------------------------------------------------------------------
#define TS 72                        // halves per smem row (144 B)
#define BUFH (128*TS*2)              // halves per stage (A then B)
#define GEMM_SMEM (3*BUFH*2)         // 110592 B
#define CSTRIDE 136                  // epilogue staging stride (halves)

template<int OUTHALF, int Kc>
__global__ void __launch_bounds__(256, 2) gemm_mma(
    const __half* __restrict__ A, const __half* __restrict__ Bw,
    const float* __restrict__ bias, const float* __restrict__ R,
    void* __restrict__ Cv, int M, int N)
{
    extern __shared__ __half sm[];
    const uint32_t sbase = smem_u32(sm);
    const int tid  = threadIdx.x;
    const int wid  = tid >> 5, lane = tid & 31;
    const int g    = lane >> 2, tg = lane & 3;
    const int wm   = (wid >> 2) << 6;
    const int wn   = (wid & 3) << 5;
    const int bm   = blockIdx.x << 7, bn = blockIdx.y << 7;  // M fastest
    const int r0   = tid >> 3, c0h = (tid & 7) << 3;
    constexpr int ntk = Kc >> 6;                 // K-tiles of 64

    // ldmatrix per-lane byte offsets
    const int lrA = lane & 15;
    const uint32_t aoff = (uint32_t)(((wm + lrA) * TS) << 1)
                        + (uint32_t)(((lane >> 4) & 1) << 4);
    const int lrB = ((lane >> 4) << 3) + (lane & 7);
    const uint32_t boffb = (uint32_t)(((wn + lrB) * TS) << 1)
                         + (uint32_t)(((lane >> 3) & 1) << 4);

    float acc[4][4][4];
#pragma unroll
    for (int mi = 0; mi < 4; mi++)
#pragma unroll
        for (int ni = 0; ni < 4; ni++)
#pragma unroll
            for (int i = 0; i < 4; i++) acc[mi][ni][i] = 0.f;

    auto cp_tile = [&](int kt, int buf) {
        const int kc = kt << 6;
        const uint32_t da = sbase + (uint32_t)((buf * BUFH + r0 * TS + c0h) << 1);
        const uint32_t db = da + (uint32_t)((128 * TS) << 1);
#pragma unroll
        for (int i = 0; i < 4; i++) {
            cp16(da + (uint32_t)(((i << 5) * TS) << 1),
                 A  + (size_t)(bm + r0 + (i << 5)) * Kc + kc + c0h);
            cp16ca(db + (uint32_t)(((i << 5) * TS) << 1),
                   Bw + (size_t)(bn + r0 + (i << 5)) * Kc + kc + c0h);
        }
        asm volatile("cp.async.commit_group;" ::: "memory");
    };

    cp_tile(0, 0);
    if (ntk > 1) cp_tile(1, 1);

#pragma unroll
    for (int kt = 0; kt < ntk; kt++) {
        const int buf = kt % 3;
        if (kt < ntk - 1)
            asm volatile("cp.async.wait_group 1;" ::: "memory");
        else
            asm volatile("cp.async.wait_group 0;" ::: "memory");
        __syncthreads();

        const uint32_t Ab = sbase + (uint32_t)((buf * BUFH) << 1);
        const uint32_t Bb = Ab + (uint32_t)((128 * TS) << 1);

        // A-fragment software pipeline over 4 k16-steps
        uint32_t afb[2][4][4];
#pragma unroll
        for (int mi = 0; mi < 4; mi++)
            ldsm4(afb[0][mi], Ab + aoff + (uint32_t)(mi * ((TS << 4) << 1)));

#pragma unroll
        for (int ks = 0; ks < 4; ks++) {
            const uint32_t kb = (uint32_t)(ks << 5);   // 16 halves = 32 B
            uint32_t bf[4][2];
#pragma unroll
            for (int p = 0; p < 2; p++) {
                uint32_t t4[4];
                ldsm4(t4, Bb + boffb + (uint32_t)(p * ((TS << 4) << 1)) + kb);
                bf[2*p][0]   = t4[0]; bf[2*p][1]   = t4[1];
                bf[2*p+1][0] = t4[2]; bf[2*p+1][1] = t4[3];
            }
            if (ks < 3) {
                const uint32_t kb2 = (uint32_t)((ks + 1) << 5);
#pragma unroll
                for (int mi = 0; mi < 4; mi++)
                    ldsm4(afb[(ks + 1) & 1][mi],
                          Ab + aoff + (uint32_t)(mi * ((TS << 4) << 1)) + kb2);
            }
#pragma unroll
            for (int ni = 0; ni < 4; ni++)
#pragma unroll
                for (int mi = 0; mi < 4; mi++)
                    mma_16x8x16_f16(acc[mi][ni], afb[ks & 1][mi], bf[ni]);

            // issue next-stage cp.async after 2 MMA batches queued
            if (ks == 1 && kt + 2 < ntk)
                cp_tile(kt + 2, (kt + 2) % 3);
        }
    }

    if (OUTHALF) {
        // stage C tile (post-bias, fp16) in smem, then coalesced 16B stores
        __syncthreads();    // all warps done reading stage buffers
#pragma unroll
        for (int mi = 0; mi < 4; mi++) {
#pragma unroll
            for (int ni = 0; ni < 4; ni++) {
                const int rl = wm + (mi << 4) + g;
                const int cl = wn + (ni << 3) + (tg << 1);
                float2 bb = *(const float2*)(bias + bn + cl);
                *(__half2*)(sm + rl * CSTRIDE + cl) =
                    __floats2half2_rn(acc[mi][ni][0] + bb.x, acc[mi][ni][1] + bb.y);
                *(__half2*)(sm + (rl + 8) * CSTRIDE + cl) =
                    __floats2half2_rn(acc[mi][ni][2] + bb.x, acc[mi][ni][3] + bb.y);
            }
        }
        __syncthreads();
        __half* Ch = (__half*)Cv;
        const int rw = tid >> 4;            // 16 rows per pass
        const int ck = (tid & 15) << 3;     // 8 halves = 16B per thread
#pragma unroll
        for (int p = 0; p < 8; p++) {
            const int r = (p << 4) + rw;
            uint4 v = *(const uint4*)(sm + r * CSTRIDE + ck);
            *(uint4*)(Ch + (size_t)(bm + r) * N + bn + ck) = v;
        }
    } else {
        // fp32 out (+residual): float2x4-lane stores are already sector-perfect
#pragma unroll
        for (int mi = 0; mi < 4; mi++) {
#pragma unroll
            for (int ni = 0; ni < 4; ni++) {
                const int row = bm + wm + (mi << 4) + g;
                const int col = bn + wn + (ni << 3) + (tg << 1);
                float2 bb = *(const float2*)(bias + col);
                float2 v0 = make_float2(acc[mi][ni][0] + bb.x, acc[mi][ni][1] + bb.y);
                float2 v1 = make_float2(acc[mi][ni][2] + bb.x, acc[mi][ni][3] + bb.y);
                float* Cf = (float*)Cv;
                float2 ra = *(const float2*)(R + (size_t)row * N + col);
                float2 rb = *(const float2*)(R + (size_t)(row + 8) * N + col);
                v0.x += ra.x; v0.y += ra.y; v1.x += rb.x; v1.y += rb.y;
                *(float2*)(Cf + (size_t)row * N + col)       = v0;
                *(float2*)(Cf + (size_t)(row + 8) * N + col) = v1;
            }
        }
    }
}

// ---------------------------------------------------------------------------
// fp16 windowed attention. 1 block = 1 (window, head, batch); 4 warps.
// S=QK^T and O=PV on m16n8k16; V via ldmatrix.trans. Output staged through
// smem (Ks region, free after S-phase) for coalesced 16B stores.
// ---------------------------------------------------------------------------
#define ATTN_SMEM (3*64*TS*2)

__global__ void __launch_bounds__(128) attn_mma(const __half* __restrict__ qkv,
                                                __half* __restrict__ out)
{
    extern __shared__ __half smh[];
    __half* Qs = smh;                // 64 x TS (rows reused for P per-warp)
    __half* Ks = smh +     64 * TS;  // reused as O staging after S-phase
    __half* Vs = smh + 2 * 64 * TS;
    const int tid  = threadIdx.x;
    const int wid  = tid >> 5, lane = tid & 31;
    const int g    = lane >> 2, tg = lane & 3;
    const int m0   = wid << 4;
    const size_t base = ((size_t)(blockIdx.z * L_ + blockIdx.x * W_)) * (3 * D_)
                        + blockIdx.y * HD_;

    const uint32_t Qb = smem_u32(Qs);
    const uint32_t Kb = smem_u32(Ks);
    const uint32_t Vb = smem_u32(Vs);

    // ldmatrix per-lane offsets
    const int lrA = lane & 15;
    const uint32_t qoff = (uint32_t)(((m0 + lrA) * TS) << 1)
                        + (uint32_t)(((lane >> 4) & 1) << 4);
    const int lrB = ((lane >> 4) << 3) + (lane & 7);
    const uint32_t koffb = (uint32_t)((lrB * TS) << 1)
                         + (uint32_t)(((lane >> 3) & 1) << 4);
    const uint32_t voffb = (uint32_t)(((((lane >> 3) & 1) * 8 + (lane & 7)) * TS) << 1)
                         + (uint32_t)(((lane >> 4) & 1) << 4);

    // load Q,K,V tiles (64 x 64 halves each), 16B chunks
    for (int i = tid; i < 64 * 8; i += 128) {
        const int r = i >> 3, c = (i & 7) << 3;
        const __half* p = qkv + base + (size_t)r * (3 * D_) + c;
        *(uint4*)(Qs + r * TS + c) = *(const uint4*)(p);
        *(uint4*)(Ks + r * TS + c) = *(const uint4*)(p + D_);
        *(uint4*)(Vs + r * TS + c) = *(const uint4*)(p + 2 * D_);
    }
    __syncthreads();

    // S = Q K^T  (contraction over hd=64: 4 k16-steps)
    float s[8][4];
#pragma unroll
    for (int t = 0; t < 8; t++)
#pragma unroll
        for (int i = 0; i < 4; i++) s[t][i] = 0.f;

#pragma unroll
    for (int ks = 0; ks < 4; ks++) {
        const uint32_t kb = (uint32_t)(ks << 5);
        uint32_t a[4], bfr[8][2];
        ldsm4(a, Qb + qoff + kb);
#pragma unroll
        for (int p = 0; p < 4; p++) {
            uint32_t t4[4];
            ldsm4(t4, Kb + koffb + (uint32_t)(p * ((TS << 4) << 1)) + kb);
            bfr[2*p][0]   = t4[0]; bfr[2*p][1]   = t4[1];
            bfr[2*p+1][0] = t4[2]; bfr[2*p+1][1] = t4[3];
        }
#pragma unroll
        for (int t = 0; t < 8; t++)
            mma_16x8x16_f16(s[t], a, bfr[t]);
    }

    // softmax over 64 cols; rows g (c0,c1) and g+8 (c2,c3)
    float mxl = -3.0e38f, mxh = -3.0e38f;
#pragma unroll
    for (int t = 0; t < 8; t++) {
#pragma unroll
        for (int i = 0; i < 4; i++) s[t][i] *= 0.125f;
        mxl = fmaxf(mxl, fmaxf(s[t][0], s[t][1]));
        mxh = fmaxf(mxh, fmaxf(s[t][2], s[t][3]));
    }
    mxl = fmaxf(mxl, __shfl_xor_sync(0xffffffffu, mxl, 1));
    mxl = fmaxf(mxl, __shfl_xor_sync(0xffffffffu, mxl, 2));
    mxh = fmaxf(mxh, __shfl_xor_sync(0xffffffffu, mxh, 1));
    mxh = fmaxf(mxh, __shfl_xor_sync(0xffffffffu, mxh, 2));

    float sl = 0.f, sh = 0.f;
#pragma unroll
    for (int t = 0; t < 8; t++) {
        s[t][0] = __expf(s[t][0] - mxl); sl += s[t][0];
        s[t][1] = __expf(s[t][1] - mxl); sl += s[t][1];
        s[t][2] = __expf(s[t][2] - mxh); sh += s[t][2];
        s[t][3] = __expf(s[t][3] - mxh); sh += s[t][3];
    }
    sl += __shfl_xor_sync(0xffffffffu, sl, 1);
    sl += __shfl_xor_sync(0xffffffffu, sl, 2);
    sh += __shfl_xor_sync(0xffffffffu, sh, 1);
    sh += __shfl_xor_sync(0xffffffffu, sh, 2);
    const float il = 1.0f / sl, ih = 1.0f / sh;

    // write P (fp16) into this warp's private Q rows
#pragma unroll
    for (int t = 0; t < 8; t++) {
        const int cc = (t << 3) + (tg << 1);
        *(__half2*)(Qs + (m0 + g) * TS + cc) =
            __floats2half2_rn(s[t][0] * il, s[t][1] * il);
        *(__half2*)(Qs + (m0 + g + 8) * TS + cc) =
            __floats2half2_rn(s[t][2] * ih, s[t][3] * ih);
    }
    __syncwarp();

    // O = P V  (contraction over 64 keys: 4 k16-steps, V via trans-ldmatrix)
    float o[8][4];
#pragma unroll
    for (int t = 0; t < 8; t++)
#pragma unroll
        for (int i = 0; i < 4; i++) o[t][i] = 0.f;

#pragma unroll
    for (int ks = 0; ks < 4; ks++) {
        uint32_t a[4];
        ldsm4(a, Qb + qoff + (uint32_t)(ks << 5));
        const uint32_t vkb = (uint32_t)(ks * ((TS << 4) << 1));  // 16 key-rows
#pragma unroll
        for (int p = 0; p < 4; p++) {
            uint32_t t4[4];
            ldsm4t(t4, Vb + voffb + vkb + (uint32_t)(p << 5));   // p*16 hd-cols
            uint32_t b0[2] = { t4[0], t4[1] };
            uint32_t b1[2] = { t4[2], t4[3] };
            mma_16x8x16_f16(o[2*p],   a, b0);
            mma_16x8x16_f16(o[2*p+1], a, b1);
        }
    }

    // stage O in Ks (all warps past S-phase after this barrier), then
    // cooperative coalesced 16B stores
    __syncthreads();
#pragma unroll
    for (int t = 0; t < 8; t++) {
        const int cc = (t << 3) + (tg << 1);
        *(__half2*)(Ks + (m0 + g) * TS + cc)       = __floats2half2_rn(o[t][0], o[t][1]);
        *(__half2*)(Ks + (m0 + g + 8) * TS + cc)   = __floats2half2_rn(o[t][2], o[t][3]);
    }
    __syncthreads();

    const size_t rowbase = (size_t)(blockIdx.z * L_ + blockIdx.x * W_);
    const int colb = blockIdx.y * HD_;
    const int rw = tid >> 3;            // 16 rows per pass
    const int ck = (tid & 7) << 3;      // 8 halves = 16B
#pragma unroll
    for (int p = 0; p < 4; p++) {
        const int r = (p << 4) + rw;
        uint4 v = *(const uint4*)(Ks + r * TS + ck);
        *(uint4*)(out + (rowbase + r) * D_ + colb + ck) = v;
    }
}

// ---------------------------------------------------------------------------
// LayerNorm: one block per 2 rows of 1024.
// ---------------------------------------------------------------------------
__global__ void __launch_bounds__(256) ln_kernel(const float* __restrict__ y,
                                                 const float* __restrict__ gamma,
                                                 const float* __restrict__ beta,
                                                 float* __restrict__ out)
{
    __shared__ float red[8];
    const int tid = threadIdx.x;
    float4 gm = *(const float4*)(gamma + (tid << 2));
    float4 be = *(const float4*)(beta  + (tid << 2));

#pragma unroll
    for (int rr = 0; rr < 2; rr++) {
        const int row = (blockIdx.x << 1) + rr;
        const float* yr = y + (size_t)row * D_;
        float4 v = *(const float4*)(yr + (tid << 2));

        float sAcc = v.x + v.y + v.z + v.w;
#pragma unroll
        for (int o = 16; o > 0; o >>= 1) sAcc += __shfl_xor_sync(0xffffffffu, sAcc, o);
        if ((tid & 31) == 0) red[tid >> 5] = sAcc;
        __syncthreads();
        float tot = 0.f;
#pragma unroll
        for (int i = 0; i < 8; i++) tot += red[i];
        const float mean = tot * (1.0f / 1024.0f);

        const float dx = v.x - mean, dy = v.y - mean, dz = v.z - mean, dw = v.w - mean;
        float s2 = dx * dx + dy * dy + dz * dz + dw * dw;
#pragma unroll
        for (int o = 16; o > 0; o >>= 1) s2 += __shfl_xor_sync(0xffffffffu, s2, o);
        __syncthreads();
        if ((tid & 31) == 0) red[tid >> 5] = s2;
        __syncthreads();
        float tot2 = 0.f;
#pragma unroll
        for (int i = 0; i < 8; i++) tot2 += red[i];
        const float rstd = rsqrtf(tot2 * (1.0f / 1024.0f) + EPS_);

        float4 o4 = make_float4(dx * rstd * gm.x + be.x,
                                dy * rstd * gm.y + be.y,
                                dz * rstd * gm.z + be.z,
                                dw * rstd * gm.w + be.w);
        *(float4*)(out + (size_t)row * D_ + (tid << 2)) = o4;
        if (rr == 0) __syncthreads();
    }
}

// ---------------------------------------------------------------------------
extern "C" void kernel_launch(void* const* d_in, const int* in_sizes, int n_in,
                              void* d_out, int out_size)
{
    const float* x     = (const float*)d_in[0];
    const float* Wqkv  = (const float*)d_in[1];
    const float* bqkv  = (const float*)d_in[2];
    const float* Wproj = (const float*)d_in[3];
    const float* bproj = (const float*)d_in[4];
    const float* gamma = (const float*)d_in[5];
    const float* beta  = (const float*)d_in[6];
    float* out = (float*)d_out;

    __half *qkv, *attn, *xh, *wq, *wp;
    float *y;
    cudaGetSymbolAddress((void**)&qkv,  g_qkvh);
    cudaGetSymbolAddress((void**)&attn, g_attnh);
    cudaGetSymbolAddress((void**)&y,    g_y);
    cudaGetSymbolAddress((void**)&xh,   g_xh);
    cudaGetSymbolAddress((void**)&wq,   g_wqh);
    cudaGetSymbolAddress((void**)&wp,   g_wph);

    cudaFuncSetAttribute((const void*)gemm_mma<1,1024>,
                         cudaFuncAttributeMaxDynamicSharedMemorySize, GEMM_SMEM);
    cudaFuncSetAttribute((const void*)gemm_mma<0,1024>,
                         cudaFuncAttributeMaxDynamicSharedMemorySize, GEMM_SMEM);
    cudaFuncSetAttribute(attn_mma, cudaFuncAttributeMaxDynamicSharedMemorySize, ATTN_SMEM);

    // 0) convert all GEMM operands to fp16 in one launch
    const int n4_all = N4_X + N4_WQ + N4_WP;
    to_half_all<<<(n4_all + 255) / 256, 256>>>(x, Wqkv, Wproj, xh, wq, wp);

    // 1) QKV projection — grid: x = M-tiles (fastest), y = N-tiles
    gemm_mma<1,1024><<<dim3(128, 24), 256, GEMM_SMEM>>>(xh, wq, bqkv,
                                                        (const float*)0, qkv,
                                                        ML_, 3 * D_);
    // 2) windowed attention (fp16 tensor cores, coalesced epilogue)
    attn_mma<<<dim3(64, 16, 4), 128, ATTN_SMEM>>>(qkv, attn);
    // 3) output projection + bias + residual — grid: x = M-tiles, y = N-tiles
    gemm_mma<0,1024><<<dim3(128, 8), 256, GEMM_SMEM>>>(attn, wp, bproj, x,
                                                       y, ML_, D_);
    // 4) layernorm (2 rows per block)
    ln_kernel<<<ML_/2, 256>>>(y, gamma, beta, out);
}